// round 9
// baseline (speedup 1.0000x reference)
#include <cuda_runtime.h>
#include <cuda_bf16.h>
#include <cstdint>

#define NUSR 100000
#define NITM 50000
#define NNODE (NUSR + NITM)
#define DD 128
#define EE 1500000
#define HALFD 64
#define KCAT 320
#define NBLK 586   // ceil(NNODE/256)

#define APAD16 20
#define APAD32 36
#define WPAD32 136
#define WPAD16 132

// weight buffer offsets (floats), plain [k][128] row-major, tf32-rounded
#define OFF_U  0
#define OFF_I  40960
#define OFF_W0 81920
#define OFF_W1 114688
#define OFF_V0 147456
#define OFF_V1 163840
#define WTOT   180224

// -------- scratch (device globals: allocation-free) --------
__device__ float g_bufA[(size_t)NNODE * DD];
__device__ float g_cat [(size_t)NNODE * KCAT];
__device__ float g_wts [WTOT];
__device__ int   g_deg[NNODE];
__device__ int   g_bsum[1024];
__device__ int   g_offs[NNODE + 1];
__device__ int   g_cursor[NNODE];
__device__ int   g_csr[EE];
__device__ __nv_bfloat16 g_ufeb[5000 * 128];
__device__ __nv_bfloat16 g_ifeb[8000 * 128];
__device__ __nv_bfloat16 g_web [30000 * 64];

// -------- tf32 helpers --------
__device__ __forceinline__ uint32_t f2tf32(float v) {
    uint32_t r;
    asm("cvt.rna.tf32.f32 %0, %1;" : "=r"(r) : "f"(v));
    return r;
}
__device__ __forceinline__ float rtf(float v) { return __uint_as_float(f2tf32(v)); }

__device__ __forceinline__ void mma_tf32(float* c, const uint32_t* a, const uint32_t* b) {
    asm volatile(
        "mma.sync.aligned.m16n8k8.row.col.f32.tf32.tf32.f32 "
        "{%0,%1,%2,%3}, {%4,%5,%6,%7}, {%8,%9}, {%0,%1,%2,%3};"
        : "+f"(c[0]), "+f"(c[1]), "+f"(c[2]), "+f"(c[3])
        : "r"(a[0]), "r"(a[1]), "r"(a[2]), "r"(a[3]), "r"(b[0]), "r"(b[1]));
}

__device__ __forceinline__ void cp16(void* smem_dst, const void* gsrc, bool pred) {
    uint32_t dst = (uint32_t)__cvta_generic_to_shared(smem_dst);
    int sz = pred ? 16 : 0;
    asm volatile("cp.async.ca.shared.global [%0], [%1], 16, %2;\n"
                 :: "r"(dst), "l"(gsrc), "r"(sz));
}
__device__ __forceinline__ void cp_commit() { asm volatile("cp.async.commit_group;\n"); }
__device__ __forceinline__ void cp_wait0()  { asm volatile("cp.async.wait_group 0;\n"); }
__device__ __forceinline__ void cp_wait1()  { asm volatile("cp.async.wait_group 1;\n"); }

// Hs swizzle: row-major [128][128], phys col = col ^ (4*(row&7))
__device__ __forceinline__ int hsw(int r, int c) { return r * 128 + (c ^ ((r & 7) << 2)); }

// -------- utility kernels --------
__global__ void zero_kernel(uint4* __restrict__ p, int n4) {
    int i = blockIdx.x * blockDim.x + threadIdx.x;
    int st = gridDim.x * blockDim.x;
    for (; i < n4; i += st) p[i] = make_uint4(0, 0, 0, 0);
}

__global__ void roundw_kernel(const float* __restrict__ uW, const float* __restrict__ iW,
                              const float* __restrict__ w0, const float* __restrict__ w1,
                              const float* __restrict__ v0, const float* __restrict__ v1) {
    int i = blockIdx.x * blockDim.x + threadIdx.x;
    if (i >= WTOT) return;
    float v;
    if      (i < OFF_I)  v = uW[i - OFF_U];
    else if (i < OFF_W0) v = iW[i - OFF_I];
    else if (i < OFF_W1) v = w0[i - OFF_W0];
    else if (i < OFF_V0) v = w1[i - OFF_W1];
    else if (i < OFF_V1) v = v0[i - OFF_V0];
    else                 v = v1[i - OFF_V1];
    g_wts[i] = rtf(v);
}

__global__ void conv_tables(const float* __restrict__ ufe, const float* __restrict__ ife,
                            const float* __restrict__ we) {
    int i = blockIdx.x * blockDim.x + threadIdx.x;
    int st = gridDim.x * blockDim.x;
    for (; i < 3584000; i += st) {
        if      (i < 640000)  g_ufeb[i]           = __float2bfloat16(ufe[i]);
        else if (i < 1664000) g_ifeb[i - 640000]  = __float2bfloat16(ife[i - 640000]);
        else                  g_web [i - 1664000] = __float2bfloat16(we [i - 1664000]);
    }
}

__global__ void deg_kernel(const int* __restrict__ dst) {
    int i = blockIdx.x * blockDim.x + threadIdx.x;
    if (i < EE) atomicAdd(&g_deg[dst[i]], 1);
}

__global__ void scan1_kernel() {
    __shared__ int sm[256];
    int tid = threadIdx.x;
    int i = blockIdx.x * 256 + tid;
    int v = (i < NNODE) ? g_deg[i] : 0;
    sm[tid] = v;
    __syncthreads();
#pragma unroll
    for (int d = 1; d < 256; d <<= 1) {
        int t = (tid >= d) ? sm[tid - d] : 0;
        __syncthreads();
        sm[tid] += t;
        __syncthreads();
    }
    if (i < NNODE) g_offs[i] = sm[tid] - v;
    if (tid == 255) g_bsum[blockIdx.x] = sm[255];
}

__global__ void scan2_kernel() {
    __shared__ int sm[1024];
    int tid = threadIdx.x;
    int v = (tid < NBLK) ? g_bsum[tid] : 0;
    sm[tid] = v;
    __syncthreads();
#pragma unroll
    for (int d = 1; d < 1024; d <<= 1) {
        int t = (tid >= d) ? sm[tid - d] : 0;
        __syncthreads();
        sm[tid] += t;
        __syncthreads();
    }
    g_bsum[tid] = sm[tid] - v;
}

__global__ void scan3_kernel() {
    int i = blockIdx.x * blockDim.x + threadIdx.x;
    if (i < NNODE) {
        int o = g_offs[i] + g_bsum[i >> 8];
        g_offs[i] = o;
        g_cursor[i] = o;
    }
    if (i == 0) g_offs[NNODE] = EE;
}

__global__ void fill_kernel(const int* __restrict__ src, const int* __restrict__ dst) {
    int i = blockIdx.x * blockDim.x + threadIdx.x;
    if (i < EE) {
        int d = dst[i];
        int pos = atomicAdd(&g_cursor[d], 1);
        g_csr[pos] = src[i];
    }
}

// -------- embedding gather from bf16 tables --------
__global__ void embed_kernel(const int* __restrict__ uf,  const int* __restrict__ itf,
                             const int* __restrict__ ut,  const int* __restrict__ it) {
    int gw   = (blockIdx.x * blockDim.x + threadIdx.x) >> 5;
    int lane = threadIdx.x & 31;
    if (gw >= NNODE) return;
    int n = gw;
    bool user = n < NUSR;
    const int* f = user ? uf + (size_t)n * 10 : itf + (size_t)(n - NUSR) * 10;
    const __nv_bfloat16* tab = user ? g_ufeb : g_ifeb;

    float4 a = make_float4(0.f, 0.f, 0.f, 0.f);
#pragma unroll
    for (int j = 0; j < 10; j++) {
        int r = __ldg(f + j);
        uint2 v = __ldg((const uint2*)(tab + (size_t)r * DD) + lane);
        float2 p0 = __bfloat1622float2(*(__nv_bfloat162*)&v.x);
        float2 p1 = __bfloat1622float2(*(__nv_bfloat162*)&v.y);
        a.x += p0.x; a.y += p0.y; a.z += p1.x; a.w += p1.y;
    }
    float* catrow = g_cat + (size_t)n * KCAT;
    a.x = rtf(a.x * 0.1f); a.y = rtf(a.y * 0.1f);
    a.z = rtf(a.z * 0.1f); a.w = rtf(a.w * 0.1f);
    ((float4*)catrow)[lane] = a;

    const int* t = user ? ut + (size_t)n * 24 : it + (size_t)(n - NUSR) * 24;
#pragma unroll
    for (int fl = 0; fl < 3; fl++) {
        float2 b = make_float2(0.f, 0.f);
#pragma unroll
        for (int w = 0; w < 8; w++) {
            int r = __ldg(t + fl * 8 + w);
            uint32_t v = __ldg((const uint32_t*)(g_web + (size_t)r * HALFD) + lane);
            float2 p = __bfloat1622float2(*(__nv_bfloat162*)&v);
            b.x += p.x; b.y += p.y;
        }
        b.x = rtf(b.x * 0.125f); b.y = rtf(b.y * 0.125f);
        ((float2*)(catrow + 128 + fl * 64))[lane] = b;
    }
}

// ======== TF32 GEMM (projection) — R5-proven: BK=32 double-buffer cp.async ========
// out[M,128] = A[M,K1] @ Wt[K1,128] + bias + addmat   (output tf32-rounded)
// dyn smem: As[2][128][APAD32] | Ws[2][32][WPAD32]
__global__ __launch_bounds__(256) void gemm_tf32(
    const float* __restrict__ A,  int K1, int woff,
    const float* __restrict__ bias,
    const float* __restrict__ addmat,
    float* __restrict__ out, int M)
{
    extern __shared__ float sm_[];
    float (*As)[128][APAD32] = (float (*)[128][APAD32])sm_;
    float (*Ws)[32][WPAD32]  = (float (*)[32][WPAD32])(sm_ + 2 * 128 * APAD32);
    const float* Wt = g_wts + woff;

    int tid  = threadIdx.x;
    int lane = tid & 31;
    int wid  = tid >> 5;
    int wm = wid & 1, wn = wid >> 1;
    int g  = lane >> 2, tg = lane & 3;
    int r0 = blockIdx.x * 128;

    float acc[4][4][4];
#pragma unroll
    for (int mt = 0; mt < 4; mt++)
#pragma unroll
        for (int nt = 0; nt < 4; nt++)
#pragma unroll
            for (int u = 0; u < 4; u++) acc[mt][nt][u] = 0.f;

    int T = K1 / 32;
    auto issue = [&](int t, int s) {
#pragma unroll
        for (int l = 0; l < 4; l++) {
            int idx = tid + l * 256;
            int m = idx >> 3, c8 = (idx & 7) * 4;
            int row = r0 + m;
            cp16(&As[s][m][c8], A + (size_t)row * K1 + t * 32 + c8, row < M);
        }
#pragma unroll
        for (int l = 0; l < 4; l++) {
            int idx = tid + l * 256;
            int k = idx >> 5, n4 = (idx & 31) * 4;
            cp16(&Ws[s][k][n4], Wt + (size_t)(t * 32 + k) * 128 + n4, true);
        }
        cp_commit();
    };

    issue(0, 0);
    for (int t = 0; t < T; t++) {
        int s = t & 1;
        if (t + 1 < T) { issue(t + 1, s ^ 1); cp_wait1(); }
        else cp_wait0();
        __syncthreads();
#pragma unroll
        for (int ks = 0; ks < 32; ks += 8) {
            uint32_t afr[4][4];
#pragma unroll
            for (int mt = 0; mt < 4; mt++) {
                int rb = wm * 64 + mt * 16 + g;
                afr[mt][0] = __float_as_uint(As[s][rb    ][ks + tg]);
                afr[mt][1] = __float_as_uint(As[s][rb + 8][ks + tg]);
                afr[mt][2] = __float_as_uint(As[s][rb    ][ks + tg + 4]);
                afr[mt][3] = __float_as_uint(As[s][rb + 8][ks + tg + 4]);
            }
            uint32_t bfr[4][2];
#pragma unroll
            for (int nt = 0; nt < 4; nt++) {
                int cb = wn * 32 + nt * 8 + g;
                bfr[nt][0] = __float_as_uint(Ws[s][ks + tg    ][cb]);
                bfr[nt][1] = __float_as_uint(Ws[s][ks + tg + 4][cb]);
            }
#pragma unroll
            for (int mt = 0; mt < 4; mt++)
#pragma unroll
                for (int nt = 0; nt < 4; nt++)
                    mma_tf32(acc[mt][nt], afr[mt], bfr[nt]);
        }
        __syncthreads();
    }

#pragma unroll
    for (int mt = 0; mt < 4; mt++) {
#pragma unroll
        for (int nt = 0; nt < 4; nt++) {
            int col = wn * 32 + nt * 8 + tg * 2;
            int rowa = r0 + wm * 64 + mt * 16 + g;
            int rowb = rowa + 8;
            float b0 = bias[col], b1 = bias[col + 1];
            if (rowa < M) {
                float x0 = rtf(acc[mt][nt][0] + b0 + addmat[(size_t)rowa * 128 + col]);
                float x1 = rtf(acc[mt][nt][1] + b1 + addmat[(size_t)rowa * 128 + col + 1]);
                *(float2*)(out + (size_t)rowa * 128 + col) = make_float2(x0, x1);
            }
            if (rowb < M) {
                float x2 = rtf(acc[mt][nt][2] + b0 + addmat[(size_t)rowb * 128 + col]);
                float x3 = rtf(acc[mt][nt][3] + b1 + addmat[(size_t)rowb * 128 + col + 1]);
                *(float2*)(out + (size_t)rowb * 128 + col) = make_float2(x2, x3);
            }
        }
    }
}

// ======== fused SAGE layer with in-kernel aggregation ========
// 1. gather agg tile (CSR mean of x rows) -> Hs (swizzled, tf32)
// 2. 24-tile GEMM pipeline:
//    t 0..7 : acc += Hs(agg) @ vW[t]         (A from smem Hs)
//    t==7   : h = relu(acc+vb) -> Hs, acc=0
//    t 8..15: acc += x @ wW[0:128]           (A via cp.async 2-stage)
//    t 16..23: acc += Hs(h) @ wW[128:256]
// W always 2-stage smem; one group {W_{t+1}, X_{t+1}} committed after barrier.
// dyn smem: As[2][128][APAD16] | Ws[2][16][WPAD16] | Hs[128*128]
template <bool RELU>
__global__ __launch_bounds__(256) void sage_layer(
    const float* __restrict__ x,
    int voff, const float* __restrict__ vb,
    int woff, const float* __restrict__ wb,
    float* __restrict__ out, int M)
{
    extern __shared__ float sm_[];
    float (*As)[128][APAD16] = (float (*)[128][APAD16])sm_;
    float (*Ws)[16][WPAD16]  = (float (*)[16][WPAD16])(sm_ + 2 * 128 * APAD16);
    float* Hs = sm_ + 2 * 128 * APAD16 + 2 * 16 * WPAD16;
    const float* vW = g_wts + voff;
    const float* wW = g_wts + woff;

    int tid  = threadIdx.x;
    int lane = tid & 31;
    int wid  = tid >> 5;
    int wm = wid & 1, wn = wid >> 1;
    int g  = lane >> 2, tg = lane & 3;
    int r0 = blockIdx.x * 128;

    auto issueW = [&](int wt, int s) {
        const float* Wp = (wt < 8) ? (vW + (size_t)wt * 16 * 128)
                                   : (wW + (size_t)(wt - 8) * 16 * 128);
#pragma unroll
        for (int l = 0; l < 2; l++) {
            int idx = tid + l * 256;
            int k = idx >> 5, n4 = (idx & 31) * 4;
            cp16(&Ws[s][k][n4], Wp + (size_t)k * 128 + n4, true);
        }
    };
    auto issueX = [&](int u, int s) {   // x k-tile u (0..7)
#pragma unroll
        for (int l = 0; l < 2; l++) {
            int idx = tid + l * 256;
            int m = idx >> 2, c4 = (idx & 3) * 4;
            int row = r0 + m;
            cp16(&As[s][m][c4], x + (size_t)row * DD + u * 16 + c4, row < M);
        }
    };

    // prefetch G0 = {W0} before gather (covers gather duration)
    issueW(0, 0);
    cp_commit();

    // ---- gather: agg rows -> Hs (swizzled, tf32-rounded) ----
    for (int r = wid; r < 128; r += 8) {
        int row = r0 + r;
        if (row < M) {
            int off = g_offs[row];
            int end = g_offs[row + 1];
            float4 a4 = make_float4(0.f, 0.f, 0.f, 0.f);
            for (int j = off; j < end; j++) {
                int s = __ldg(&g_csr[j]);
                float4 v = __ldg((const float4*)(x + (size_t)s * DD) + lane);
                a4.x += v.x; a4.y += v.y; a4.z += v.z; a4.w += v.w;
            }
            float sc = 1.0f / fmaxf((float)(end - off), 1.0f);
            a4.x = rtf(a4.x * sc); a4.y = rtf(a4.y * sc);
            a4.z = rtf(a4.z * sc); a4.w = rtf(a4.w * sc);
            *((float4*)(Hs + r * 128) + (lane ^ (r & 7))) = a4;
        }
    }

    float acc[4][4][4];
#pragma unroll
    for (int mt = 0; mt < 4; mt++)
#pragma unroll
        for (int nt = 0; nt < 4; nt++)
#pragma unroll
            for (int u = 0; u < 4; u++) acc[mt][nt][u] = 0.f;

    for (int t = 0; t < 24; t++) {
        cp_wait0();
        __syncthreads();
        if (t + 1 < 24) {
            issueW(t + 1, (t + 1) & 1);
            if (t + 1 >= 8 && t + 1 < 16) issueX(t + 1 - 8, (t + 1) & 1);
            cp_commit();
        }

        int sw = t & 1;
        int hc = (t < 8) ? t * 16 : (t - 16) * 16;
#pragma unroll
        for (int ks = 0; ks < 16; ks += 8) {
            uint32_t afr[4][4];
#pragma unroll
            for (int mt = 0; mt < 4; mt++) {
                int rb = wm * 64 + mt * 16 + g;
                if (t >= 8 && t < 16) {
                    afr[mt][0] = __float_as_uint(As[sw][rb    ][ks + tg]);
                    afr[mt][1] = __float_as_uint(As[sw][rb + 8][ks + tg]);
                    afr[mt][2] = __float_as_uint(As[sw][rb    ][ks + tg + 4]);
                    afr[mt][3] = __float_as_uint(As[sw][rb + 8][ks + tg + 4]);
                } else {
                    afr[mt][0] = __float_as_uint(Hs[hsw(rb,     hc + ks + tg)]);
                    afr[mt][1] = __float_as_uint(Hs[hsw(rb + 8, hc + ks + tg)]);
                    afr[mt][2] = __float_as_uint(Hs[hsw(rb,     hc + ks + tg + 4)]);
                    afr[mt][3] = __float_as_uint(Hs[hsw(rb + 8, hc + ks + tg + 4)]);
                }
            }
            uint32_t bfr[4][2];
#pragma unroll
            for (int nt = 0; nt < 4; nt++) {
                int cb = wn * 32 + nt * 8 + g;
                bfr[nt][0] = __float_as_uint(Ws[sw][ks + tg    ][cb]);
                bfr[nt][1] = __float_as_uint(Ws[sw][ks + tg + 4][cb]);
            }
#pragma unroll
            for (int mt = 0; mt < 4; mt++)
#pragma unroll
                for (int nt = 0; nt < 4; nt++)
                    mma_tf32(acc[mt][nt], afr[mt], bfr[nt]);
        }

        if (t == 7) {
            // all phase-1 reads of Hs done by everyone, then overwrite with h
            __syncthreads();
#pragma unroll
            for (int mt = 0; mt < 4; mt++) {
#pragma unroll
                for (int nt = 0; nt < 4; nt++) {
                    int col = wn * 32 + nt * 8 + tg * 2;
                    int ra = wm * 64 + mt * 16 + g;
                    float b0 = vb[col], b1 = vb[col + 1];
                    Hs[hsw(ra,     col    )] = rtf(fmaxf(acc[mt][nt][0] + b0, 0.f));
                    Hs[hsw(ra,     col + 1)] = rtf(fmaxf(acc[mt][nt][1] + b1, 0.f));
                    Hs[hsw(ra + 8, col    )] = rtf(fmaxf(acc[mt][nt][2] + b0, 0.f));
                    Hs[hsw(ra + 8, col + 1)] = rtf(fmaxf(acc[mt][nt][3] + b1, 0.f));
#pragma unroll
                    for (int u = 0; u < 4; u++) acc[mt][nt][u] = 0.f;
                }
            }
        }
    }

    // epilogue
#pragma unroll
    for (int mt = 0; mt < 4; mt++) {
#pragma unroll
        for (int nt = 0; nt < 4; nt++) {
            int col = wn * 32 + nt * 8 + tg * 2;
            int rowa = r0 + wm * 64 + mt * 16 + g;
            int rowb = rowa + 8;
            float b0 = wb[col], b1 = wb[col + 1];
            if (rowa < M) {
                float x0 = acc[mt][nt][0] + b0;
                float x1 = acc[mt][nt][1] + b1;
                if (RELU) { x0 = rtf(fmaxf(x0, 0.f)); x1 = rtf(fmaxf(x1, 0.f)); }
                *(float2*)(out + (size_t)rowa * 128 + col) = make_float2(x0, x1);
            }
            if (rowb < M) {
                float x2 = acc[mt][nt][2] + b0;
                float x3 = acc[mt][nt][3] + b1;
                if (RELU) { x2 = rtf(fmaxf(x2, 0.f)); x3 = rtf(fmaxf(x3, 0.f)); }
                *(float2*)(out + (size_t)rowb * 128 + col) = make_float2(x2, x3);
            }
        }
    }
}

// -------- launch --------
extern "C" void kernel_launch(void* const* d_in, const int* in_sizes, int n_in,
                              void* d_out, int out_size) {
    const int*   edge          = (const int*)d_in[0];
    const int*   src           = edge;
    const int*   dstp          = edge + EE;
    const int*   user_features = (const int*)d_in[1];
    const int*   item_features = (const int*)d_in[2];
    const int*   user_text     = (const int*)d_in[3];
    const int*   item_text     = (const int*)d_in[4];
    const float* user_id_emb   = (const float*)d_in[5];
    const float* item_id_emb   = (const float*)d_in[6];
    const float* user_feat_emb = (const float*)d_in[7];
    const float* item_feat_emb = (const float*)d_in[8];
    const float* word_emb      = (const float*)d_in[9];
    const float* user_projW    = (const float*)d_in[10];
    const float* user_projb    = (const float*)d_in[11];
    const float* item_projW    = (const float*)d_in[12];
    const float* item_projb    = (const float*)d_in[13];
    const float* w0W = (const float*)d_in[14];
    const float* w0b = (const float*)d_in[15];
    const float* w1W = (const float*)d_in[16];
    const float* w1b = (const float*)d_in[17];
    const float* v0W = (const float*)d_in[18];
    const float* v0b = (const float*)d_in[19];
    const float* v1W = (const float*)d_in[20];
    const float* v1b = (const float*)d_in[21];

    float *pA, *pcat;
    int   *pdeg;
    cudaGetSymbolAddress((void**)&pA,   g_bufA);
    cudaGetSymbolAddress((void**)&pcat, g_cat);
    cudaGetSymbolAddress((void**)&pdeg, g_deg);

    const int GEMM_SMEM = (2 * 128 * APAD32 + 2 * 32 * WPAD32) * 4;             // 71680
    const int SAGE_SMEM = (2 * 128 * APAD16 + 2 * 16 * WPAD16 + 128 * 128) * 4; // 102912
    cudaFuncSetAttribute(gemm_tf32, cudaFuncAttributeMaxDynamicSharedMemorySize, GEMM_SMEM);
    cudaFuncSetAttribute(sage_layer<true>,  cudaFuncAttributeMaxDynamicSharedMemorySize, SAGE_SMEM);
    cudaFuncSetAttribute(sage_layer<false>, cudaFuncAttributeMaxDynamicSharedMemorySize, SAGE_SMEM);

    // order: launch index 3 = user projection GEMM (profiler slot)
    roundw_kernel<<<(WTOT + 255) / 256, 256>>>(user_projW, item_projW,       // 0
                                               w0W, w1W, v0W, v1W);
    conv_tables<<<2048, 256>>>(user_feat_emb, item_feat_emb, word_emb);      // 1
    embed_kernel<<<(NNODE * 32 + 255) / 256, 256>>>(                         // 2
        user_features, item_features, user_text, item_text);
    gemm_tf32<<<(NUSR + 127) / 128, 256, GEMM_SMEM>>>(                       // 3 (profiled)
        pcat, KCAT, OFF_U, user_projb, user_id_emb, pA, NUSR);
    gemm_tf32<<<(NITM + 127) / 128, 256, GEMM_SMEM>>>(                       // 4
        pcat + (size_t)NUSR * KCAT, KCAT, OFF_I, item_projb, item_id_emb,
        pA + (size_t)NUSR * DD, NITM);
    zero_kernel<<<64, 256>>>((uint4*)pdeg, NNODE / 4);                       // 5
    deg_kernel<<<(EE + 255) / 256, 256>>>(dstp);                             // 6
    scan1_kernel<<<NBLK, 256>>>();                                           // 7
    scan2_kernel<<<1, 1024>>>();                                             // 8
    scan3_kernel<<<(NNODE + 255) / 256, 256>>>();                            // 9
    fill_kernel<<<(EE + 255) / 256, 256>>>(src, dstp);                       // 10

    // ----- layer 0: x=pA -> pcat (agg fused inside) -----
    sage_layer<true><<<(NNODE + 127) / 128, 256, SAGE_SMEM>>>(               // 11
        pA, OFF_V0, v0b, OFF_W0, w0b, pcat, NNODE);

    // ----- layer 1: x=pcat -> d_out -----
    sage_layer<false><<<(NNODE + 127) / 128, 256, SAGE_SMEM>>>(              // 12
        pcat, OFF_V1, v1b, OFF_W1, w1b, (float*)d_out, NNODE);
}

// round 10
// speedup vs baseline: 1.1456x; 1.1456x over previous
#include <cuda_runtime.h>
#include <cuda_bf16.h>
#include <cstdint>

#define NUSR 100000
#define NITM 50000
#define NNODE (NUSR + NITM)
#define DD 128
#define EE 1500000
#define HALFD 64
#define KCAT 320
#define NBLK 586     // ceil(NNODE/256)
#define UBLKS 782    // ceil(NUSR/128)
#define IBLKS 391    // ceil(NITM/128)

#define APAD16 20
#define APAD32 36
#define WPAD 136

// weight buffer offsets (floats), plain [k][128] row-major, tf32-rounded
#define OFF_U  0
#define OFF_I  40960
#define OFF_W0 81920
#define OFF_W1 114688
#define OFF_V0 147456
#define OFF_V1 163840
#define WTOT   180224

// -------- scratch (device globals: allocation-free) --------
__device__ float g_bufA[(size_t)NNODE * DD];
__device__ float g_bufB[(size_t)NNODE * DD];
__device__ float g_cat [(size_t)NNODE * KCAT];
__device__ float g_wts [WTOT];
__device__ int   g_deg[NNODE];
__device__ int   g_bsum[1024];
__device__ int   g_offs[NNODE + 1];
__device__ int   g_cursor[NNODE];
__device__ int   g_csr[EE];
__device__ __nv_bfloat16 g_ufeb[5000 * 128];
__device__ __nv_bfloat16 g_ifeb[8000 * 128];
__device__ __nv_bfloat16 g_web [30000 * 64];

// -------- tf32 helpers --------
__device__ __forceinline__ uint32_t f2tf32(float v) {
    uint32_t r;
    asm("cvt.rna.tf32.f32 %0, %1;" : "=r"(r) : "f"(v));
    return r;
}
__device__ __forceinline__ float rtf(float v) { return __uint_as_float(f2tf32(v)); }

__device__ __forceinline__ void mma_tf32(float* c, const uint32_t* a, const uint32_t* b) {
    asm volatile(
        "mma.sync.aligned.m16n8k8.row.col.f32.tf32.tf32.f32 "
        "{%0,%1,%2,%3}, {%4,%5,%6,%7}, {%8,%9}, {%0,%1,%2,%3};"
        : "+f"(c[0]), "+f"(c[1]), "+f"(c[2]), "+f"(c[3])
        : "r"(a[0]), "r"(a[1]), "r"(a[2]), "r"(a[3]), "r"(b[0]), "r"(b[1]));
}

__device__ __forceinline__ void cp16(void* smem_dst, const void* gsrc, bool pred) {
    uint32_t dst = (uint32_t)__cvta_generic_to_shared(smem_dst);
    int sz = pred ? 16 : 0;
    asm volatile("cp.async.ca.shared.global [%0], [%1], 16, %2;\n"
                 :: "r"(dst), "l"(gsrc), "r"(sz));
}
__device__ __forceinline__ void cp_commit() { asm volatile("cp.async.commit_group;\n"); }
__device__ __forceinline__ void cp_wait0()  { asm volatile("cp.async.wait_group 0;\n"); }
__device__ __forceinline__ void cp_wait1()  { asm volatile("cp.async.wait_group 1;\n"); }
__device__ __forceinline__ void cp_wait2()  { asm volatile("cp.async.wait_group 2;\n"); }
__device__ __forceinline__ void cp_wait3()  { asm volatile("cp.async.wait_group 3;\n"); }

// Hs swizzle: row-major [128][128], phys col = col ^ (4*(row&7))
__device__ __forceinline__ int hsw(int r, int c) { return r * 128 + (c ^ ((r & 7) << 2)); }

// -------- utility kernels --------
__global__ void zero_kernel(uint4* __restrict__ p, int n4) {
    int i = blockIdx.x * blockDim.x + threadIdx.x;
    int st = gridDim.x * blockDim.x;
    for (; i < n4; i += st) p[i] = make_uint4(0, 0, 0, 0);
}

__global__ void roundw_kernel(const float* __restrict__ uW, const float* __restrict__ iW,
                              const float* __restrict__ w0, const float* __restrict__ w1,
                              const float* __restrict__ v0, const float* __restrict__ v1) {
    int i = blockIdx.x * blockDim.x + threadIdx.x;
    if (i >= WTOT) return;
    float v;
    if      (i < OFF_I)  v = uW[i - OFF_U];
    else if (i < OFF_W0) v = iW[i - OFF_I];
    else if (i < OFF_W1) v = w0[i - OFF_W0];
    else if (i < OFF_V0) v = w1[i - OFF_W1];
    else if (i < OFF_V1) v = v0[i - OFF_V0];
    else                 v = v1[i - OFF_V1];
    g_wts[i] = rtf(v);
}

__global__ void conv_tables(const float* __restrict__ ufe, const float* __restrict__ ife,
                            const float* __restrict__ we) {
    int i = blockIdx.x * blockDim.x + threadIdx.x;
    int st = gridDim.x * blockDim.x;
    for (; i < 3584000; i += st) {
        if      (i < 640000)  g_ufeb[i]           = __float2bfloat16(ufe[i]);
        else if (i < 1664000) g_ifeb[i - 640000]  = __float2bfloat16(ife[i - 640000]);
        else                  g_web [i - 1664000] = __float2bfloat16(we [i - 1664000]);
    }
}

__global__ void deg_kernel(const int* __restrict__ dst) {
    int i = blockIdx.x * blockDim.x + threadIdx.x;
    if (i < EE) atomicAdd(&g_deg[dst[i]], 1);
}

__global__ void scan1_kernel() {
    __shared__ int sm[256];
    int tid = threadIdx.x;
    int i = blockIdx.x * 256 + tid;
    int v = (i < NNODE) ? g_deg[i] : 0;
    sm[tid] = v;
    __syncthreads();
#pragma unroll
    for (int d = 1; d < 256; d <<= 1) {
        int t = (tid >= d) ? sm[tid - d] : 0;
        __syncthreads();
        sm[tid] += t;
        __syncthreads();
    }
    if (i < NNODE) g_offs[i] = sm[tid] - v;
    if (tid == 255) g_bsum[blockIdx.x] = sm[255];
}

__global__ void scan2_kernel() {
    __shared__ int sm[1024];
    int tid = threadIdx.x;
    int v = (tid < NBLK) ? g_bsum[tid] : 0;
    sm[tid] = v;
    __syncthreads();
#pragma unroll
    for (int d = 1; d < 1024; d <<= 1) {
        int t = (tid >= d) ? sm[tid - d] : 0;
        __syncthreads();
        sm[tid] += t;
        __syncthreads();
    }
    g_bsum[tid] = sm[tid] - v;
}

__global__ void scan3_kernel() {
    int i = blockIdx.x * blockDim.x + threadIdx.x;
    if (i < NNODE) {
        int o = g_offs[i] + g_bsum[i >> 8];
        g_offs[i] = o;
        g_cursor[i] = o;
    }
    if (i == 0) g_offs[NNODE] = EE;
}

__global__ void fill_kernel(const int* __restrict__ src, const int* __restrict__ dst) {
    int i = blockIdx.x * blockDim.x + threadIdx.x;
    if (i < EE) {
        int d = dst[i];
        int pos = atomicAdd(&g_cursor[d], 1);
        g_csr[pos] = src[i];
    }
}

// -------- gather aggregation (warp per node), invdeg from CSR offsets --------
__global__ void agg_kernel(const float* __restrict__ x, float* __restrict__ out) {
    int gw   = (blockIdx.x * blockDim.x + threadIdx.x) >> 5;
    int lane = threadIdx.x & 31;
    if (gw >= NNODE) return;
    int off = g_offs[gw];
    int end = g_offs[gw + 1];
    float4 acc = make_float4(0.f, 0.f, 0.f, 0.f);
    for (int j = off; j < end; j++) {
        int s = __ldg(&g_csr[j]);
        float4 v = __ldg((const float4*)(x + (size_t)s * DD) + lane);
        acc.x += v.x; acc.y += v.y; acc.z += v.z; acc.w += v.w;
    }
    float sc = 1.0f / fmaxf((float)(end - off), 1.0f);
    acc.x = rtf(acc.x * sc); acc.y = rtf(acc.y * sc);
    acc.z = rtf(acc.z * sc); acc.w = rtf(acc.w * sc);
    *((float4*)(out + (size_t)gw * DD) + lane) = acc;
}

// -------- embedding gather from bf16 tables --------
__global__ void embed_kernel(const int* __restrict__ uf,  const int* __restrict__ itf,
                             const int* __restrict__ ut,  const int* __restrict__ it) {
    int gw   = (blockIdx.x * blockDim.x + threadIdx.x) >> 5;
    int lane = threadIdx.x & 31;
    if (gw >= NNODE) return;
    int n = gw;
    bool user = n < NUSR;
    const int* f = user ? uf + (size_t)n * 10 : itf + (size_t)(n - NUSR) * 10;
    const __nv_bfloat16* tab = user ? g_ufeb : g_ifeb;

    float4 a = make_float4(0.f, 0.f, 0.f, 0.f);
#pragma unroll
    for (int j = 0; j < 10; j++) {
        int r = __ldg(f + j);
        uint2 v = __ldg((const uint2*)(tab + (size_t)r * DD) + lane);
        float2 p0 = __bfloat1622float2(*(__nv_bfloat162*)&v.x);
        float2 p1 = __bfloat1622float2(*(__nv_bfloat162*)&v.y);
        a.x += p0.x; a.y += p0.y; a.z += p1.x; a.w += p1.y;
    }
    float* catrow = g_cat + (size_t)n * KCAT;
    a.x = rtf(a.x * 0.1f); a.y = rtf(a.y * 0.1f);
    a.z = rtf(a.z * 0.1f); a.w = rtf(a.w * 0.1f);
    ((float4*)catrow)[lane] = a;

    const int* t = user ? ut + (size_t)n * 24 : it + (size_t)(n - NUSR) * 24;
#pragma unroll
    for (int fl = 0; fl < 3; fl++) {
        float2 b = make_float2(0.f, 0.f);
#pragma unroll
        for (int w = 0; w < 8; w++) {
            int r = __ldg(t + fl * 8 + w);
            uint32_t v = __ldg((const uint32_t*)(g_web + (size_t)r * HALFD) + lane);
            float2 p = __bfloat1622float2(*(__nv_bfloat162*)&v);
            b.x += p.x; b.y += p.y;
        }
        b.x = rtf(b.x * 0.125f); b.y = rtf(b.y * 0.125f);
        ((float2*)(catrow + 128 + fl * 64))[lane] = b;
    }
}

// ======== merged projection GEMM (R6 core): BK=32, A dist-2 / W dist-1 ========
// blocks [0,UBLKS): user side; [UBLKS,UBLKS+IBLKS): item side
// dyn smem: As[3][128][APAD32] | Ws[2][32][WPAD]
__global__ __launch_bounds__(256) void gemm_proj(
    const float* __restrict__ ubias, const float* __restrict__ ibias,
    const float* __restrict__ uid,   const float* __restrict__ iid,
    float* __restrict__ outbase)
{
    extern __shared__ float sm_[];
    float (*As)[128][APAD32] = (float (*)[128][APAD32])sm_;
    float (*Ws)[32][WPAD]    = (float (*)[32][WPAD])(sm_ + 3 * 128 * APAD32);

    bool user = blockIdx.x < UBLKS;
    const float* A      = user ? g_cat : g_cat + (size_t)NUSR * KCAT;
    const float* Wt     = g_wts + (user ? OFF_U : OFF_I);
    const float* bias   = user ? ubias : ibias;
    const float* addmat = user ? uid : iid;
    float* out          = user ? outbase : outbase + (size_t)NUSR * DD;
    int M               = user ? NUSR : NITM;
    int r0              = (user ? blockIdx.x : blockIdx.x - UBLKS) * 128;

    int tid  = threadIdx.x;
    int lane = tid & 31;
    int wid  = tid >> 5;
    int wm = wid & 1, wn = wid >> 1;
    int g  = lane >> 2, tg = lane & 3;

    float acc[4][4][4];
#pragma unroll
    for (int mt = 0; mt < 4; mt++)
#pragma unroll
        for (int nt = 0; nt < 4; nt++)
#pragma unroll
            for (int u = 0; u < 4; u++) acc[mt][nt][u] = 0.f;

    const int T = KCAT / 32;
    auto issueA = [&](int t, int s) {
#pragma unroll
        for (int l = 0; l < 4; l++) {
            int idx = tid + l * 256;
            int m = idx >> 3, c8 = (idx & 7) * 4;
            int row = r0 + m;
            cp16(&As[s][m][c8], A + (size_t)row * KCAT + t * 32 + c8, row < M);
        }
        cp_commit();
    };
    auto issueW = [&](int t, int s) {
#pragma unroll
        for (int l = 0; l < 4; l++) {
            int idx = tid + l * 256;
            int k = idx >> 5, n4 = (idx & 31) * 4;
            cp16(&Ws[s][k][n4], Wt + (size_t)(t * 32 + k) * 128 + n4, true);
        }
        cp_commit();
    };

    issueW(0, 0);
    issueA(0, 0);
    issueA(1, 1);
    for (int t = 0; t < T; t++) {
        int sa = t % 3, sw = t & 1;
        if (t + 1 < T) issueW(t + 1, (t + 1) & 1);
        if (t + 2 < T) issueA(t + 2, (t + 2) % 3);
        if (t + 2 < T) cp_wait3();
        else if (t + 1 < T) cp_wait2();
        else cp_wait0();
        __syncthreads();
#pragma unroll
        for (int ks = 0; ks < 32; ks += 8) {
            uint32_t afr[4][4];
#pragma unroll
            for (int mt = 0; mt < 4; mt++) {
                int rb = wm * 64 + mt * 16 + g;
                afr[mt][0] = __float_as_uint(As[sa][rb    ][ks + tg]);
                afr[mt][1] = __float_as_uint(As[sa][rb + 8][ks + tg]);
                afr[mt][2] = __float_as_uint(As[sa][rb    ][ks + tg + 4]);
                afr[mt][3] = __float_as_uint(As[sa][rb + 8][ks + tg + 4]);
            }
            uint32_t bfr[4][2];
#pragma unroll
            for (int nt = 0; nt < 4; nt++) {
                int cb = wn * 32 + nt * 8 + g;
                bfr[nt][0] = __float_as_uint(Ws[sw][ks + tg    ][cb]);
                bfr[nt][1] = __float_as_uint(Ws[sw][ks + tg + 4][cb]);
            }
#pragma unroll
            for (int mt = 0; mt < 4; mt++)
#pragma unroll
                for (int nt = 0; nt < 4; nt++)
                    mma_tf32(acc[mt][nt], afr[mt], bfr[nt]);
        }
        __syncthreads();
    }

#pragma unroll
    for (int mt = 0; mt < 4; mt++) {
#pragma unroll
        for (int nt = 0; nt < 4; nt++) {
            int col = wn * 32 + nt * 8 + tg * 2;
            int rowa = r0 + wm * 64 + mt * 16 + g;
            int rowb = rowa + 8;
            float b0 = bias[col], b1 = bias[col + 1];
            if (rowa < M) {
                float x0 = rtf(acc[mt][nt][0] + b0 + addmat[(size_t)rowa * 128 + col]);
                float x1 = rtf(acc[mt][nt][1] + b1 + addmat[(size_t)rowa * 128 + col + 1]);
                *(float2*)(out + (size_t)rowa * 128 + col) = make_float2(x0, x1);
            }
            if (rowb < M) {
                float x2 = rtf(acc[mt][nt][2] + b0 + addmat[(size_t)rowb * 128 + col]);
                float x3 = rtf(acc[mt][nt][3] + b1 + addmat[(size_t)rowb * 128 + col + 1]);
                *(float2*)(out + (size_t)rowb * 128 + col) = make_float2(x2, x3);
            }
        }
    }
}

// ======== fused SAGE layer (R6 core): unified 24-tile pipeline, A dist-2 / W dist-1 ========
// dyn smem: As[3][128][APAD16] | Ws[2][16][WPAD] | Hs[128*128 swizzled]
template <bool RELU>
__global__ __launch_bounds__(256) void sage_layer(
    const float* __restrict__ agg, const float* __restrict__ x,
    int voff, const float* __restrict__ vb,
    int woff, const float* __restrict__ wb,
    float* __restrict__ out, int M)
{
    extern __shared__ float sm_[];
    float (*As)[128][APAD16] = (float (*)[128][APAD16])sm_;
    float (*Ws)[16][WPAD]    = (float (*)[16][WPAD])(sm_ + 3 * 128 * APAD16);
    float* Hs                = sm_ + 3 * 128 * APAD16 + 2 * 16 * WPAD;
    const float* vW = g_wts + voff;
    const float* wW = g_wts + woff;

    int tid  = threadIdx.x;
    int lane = tid & 31;
    int wid  = tid >> 5;
    int wm = wid & 1, wn = wid >> 1;
    int g  = lane >> 2, tg = lane & 3;
    int r0 = blockIdx.x * 128;

    float acc[4][4][4];
#pragma unroll
    for (int mt = 0; mt < 4; mt++)
#pragma unroll
        for (int nt = 0; nt < 4; nt++)
#pragma unroll
            for (int u = 0; u < 4; u++) acc[mt][nt][u] = 0.f;

    auto issueA = [&](int at, int s) {
        const float* Ap = (at < 8) ? agg : x;
        int kt = (at < 8) ? at : at - 8;
#pragma unroll
        for (int l = 0; l < 2; l++) {
            int idx = tid + l * 256;
            int m = idx >> 2, c4 = (idx & 3) * 4;
            int row = r0 + m;
            cp16(&As[s][m][c4], Ap + (size_t)row * DD + kt * 16 + c4, row < M);
        }
        cp_commit();
    };
    auto issueW = [&](int wt, int s) {
        const float* Wp = (wt < 8) ? (vW + (size_t)wt * 2048)
                                   : (wW + (size_t)(wt - 8) * 2048);
#pragma unroll
        for (int l = 0; l < 2; l++) {
            int idx = tid + l * 256;
            int k = idx >> 5, n4 = (idx & 31) * 4;
            cp16(&Ws[s][k][n4], Wp + (size_t)k * 128 + n4, true);
        }
        cp_commit();
    };

    issueW(0, 0);
    issueA(0, 0);
    issueA(1, 1);

    for (int t = 0; t < 24; t++) {
        int sa = t % 3, sw = t & 1;
        if (t + 1 < 24) issueW(t + 1, (t + 1) & 1);
        if (t + 2 < 16) issueA(t + 2, (t + 2) % 3);
        if (t < 14) cp_wait3();
        else if (t == 14) cp_wait2();
        else if (t < 23) cp_wait1();
        else cp_wait0();
        __syncthreads();

        int hc = (t - 16) * 16;
#pragma unroll
        for (int ks = 0; ks < 16; ks += 8) {
            uint32_t afr[4][4];
#pragma unroll
            for (int mt = 0; mt < 4; mt++) {
                int rb = wm * 64 + mt * 16 + g;
                if (t < 16) {
                    afr[mt][0] = __float_as_uint(As[sa][rb    ][ks + tg]);
                    afr[mt][1] = __float_as_uint(As[sa][rb + 8][ks + tg]);
                    afr[mt][2] = __float_as_uint(As[sa][rb    ][ks + tg + 4]);
                    afr[mt][3] = __float_as_uint(As[sa][rb + 8][ks + tg + 4]);
                } else {
                    afr[mt][0] = __float_as_uint(Hs[hsw(rb,     hc + ks + tg)]);
                    afr[mt][1] = __float_as_uint(Hs[hsw(rb + 8, hc + ks + tg)]);
                    afr[mt][2] = __float_as_uint(Hs[hsw(rb,     hc + ks + tg + 4)]);
                    afr[mt][3] = __float_as_uint(Hs[hsw(rb + 8, hc + ks + tg + 4)]);
                }
            }
            uint32_t bfr[4][2];
#pragma unroll
            for (int nt = 0; nt < 4; nt++) {
                int cb = wn * 32 + nt * 8 + g;
                bfr[nt][0] = __float_as_uint(Ws[sw][ks + tg    ][cb]);
                bfr[nt][1] = __float_as_uint(Ws[sw][ks + tg + 4][cb]);
            }
#pragma unroll
            for (int mt = 0; mt < 4; mt++)
#pragma unroll
                for (int nt = 0; nt < 4; nt++)
                    mma_tf32(acc[mt][nt], afr[mt], bfr[nt]);
        }

        if (t == 7) {
#pragma unroll
            for (int mt = 0; mt < 4; mt++) {
#pragma unroll
                for (int nt = 0; nt < 4; nt++) {
                    int col = wn * 32 + nt * 8 + tg * 2;
                    int ra = wm * 64 + mt * 16 + g;
                    float b0 = vb[col], b1 = vb[col + 1];
                    Hs[hsw(ra,     col    )] = rtf(fmaxf(acc[mt][nt][0] + b0, 0.f));
                    Hs[hsw(ra,     col + 1)] = rtf(fmaxf(acc[mt][nt][1] + b1, 0.f));
                    Hs[hsw(ra + 8, col    )] = rtf(fmaxf(acc[mt][nt][2] + b0, 0.f));
                    Hs[hsw(ra + 8, col + 1)] = rtf(fmaxf(acc[mt][nt][3] + b1, 0.f));
#pragma unroll
                    for (int u = 0; u < 4; u++) acc[mt][nt][u] = 0.f;
                }
            }
        }
        __syncthreads();
    }

#pragma unroll
    for (int mt = 0; mt < 4; mt++) {
#pragma unroll
        for (int nt = 0; nt < 4; nt++) {
            int col = wn * 32 + nt * 8 + tg * 2;
            int rowa = r0 + wm * 64 + mt * 16 + g;
            int rowb = rowa + 8;
            float b0 = wb[col], b1 = wb[col + 1];
            if (rowa < M) {
                float x0 = acc[mt][nt][0] + b0;
                float x1 = acc[mt][nt][1] + b1;
                if (RELU) { x0 = rtf(fmaxf(x0, 0.f)); x1 = rtf(fmaxf(x1, 0.f)); }
                *(float2*)(out + (size_t)rowa * 128 + col) = make_float2(x0, x1);
            }
            if (rowb < M) {
                float x2 = acc[mt][nt][2] + b0;
                float x3 = acc[mt][nt][3] + b1;
                if (RELU) { x2 = rtf(fmaxf(x2, 0.f)); x3 = rtf(fmaxf(x3, 0.f)); }
                *(float2*)(out + (size_t)rowb * 128 + col) = make_float2(x2, x3);
            }
        }
    }
}

// -------- launch --------
extern "C" void kernel_launch(void* const* d_in, const int* in_sizes, int n_in,
                              void* d_out, int out_size) {
    const int*   edge          = (const int*)d_in[0];
    const int*   src           = edge;
    const int*   dstp          = edge + EE;
    const int*   user_features = (const int*)d_in[1];
    const int*   item_features = (const int*)d_in[2];
    const int*   user_text     = (const int*)d_in[3];
    const int*   item_text     = (const int*)d_in[4];
    const float* user_id_emb   = (const float*)d_in[5];
    const float* item_id_emb   = (const float*)d_in[6];
    const float* user_feat_emb = (const float*)d_in[7];
    const float* item_feat_emb = (const float*)d_in[8];
    const float* word_emb      = (const float*)d_in[9];
    const float* user_projW    = (const float*)d_in[10];
    const float* user_projb    = (const float*)d_in[11];
    const float* item_projW    = (const float*)d_in[12];
    const float* item_projb    = (const float*)d_in[13];
    const float* w0W = (const float*)d_in[14];
    const float* w0b = (const float*)d_in[15];
    const float* w1W = (const float*)d_in[16];
    const float* w1b = (const float*)d_in[17];
    const float* v0W = (const float*)d_in[18];
    const float* v0b = (const float*)d_in[19];
    const float* v1W = (const float*)d_in[20];
    const float* v1b = (const float*)d_in[21];

    float *pA, *pB, *pcat;
    int   *pdeg;
    cudaGetSymbolAddress((void**)&pA,   g_bufA);
    cudaGetSymbolAddress((void**)&pB,   g_bufB);
    cudaGetSymbolAddress((void**)&pcat, g_cat);
    cudaGetSymbolAddress((void**)&pdeg, g_deg);

    const int GEMM_SMEM = (3 * 128 * APAD32 + 2 * 32 * WPAD) * 4;               // 90112
    const int SAGE_SMEM = (3 * 128 * APAD16 + 2 * 16 * WPAD + 128 * 128) * 4;   // 113152
    cudaFuncSetAttribute(gemm_proj, cudaFuncAttributeMaxDynamicSharedMemorySize, GEMM_SMEM);
    cudaFuncSetAttribute(sage_layer<true>,  cudaFuncAttributeMaxDynamicSharedMemorySize, SAGE_SMEM);
    cudaFuncSetAttribute(sage_layer<false>, cudaFuncAttributeMaxDynamicSharedMemorySize, SAGE_SMEM);

    // order: launch index 3 = merged projection GEMM (profiler slot)
    roundw_kernel<<<(WTOT + 255) / 256, 256>>>(user_projW, item_projW,       // 0
                                               w0W, w1W, v0W, v1W);
    conv_tables<<<2048, 256>>>(user_feat_emb, item_feat_emb, word_emb);      // 1
    embed_kernel<<<(NNODE * 32 + 255) / 256, 256>>>(                         // 2
        user_features, item_features, user_text, item_text);
    gemm_proj<<<UBLKS + IBLKS, 256, GEMM_SMEM>>>(                            // 3 (profiled)
        user_projb, item_projb, user_id_emb, item_id_emb, pA);
    zero_kernel<<<64, 256>>>((uint4*)pdeg, NNODE / 4);                       // 4
    deg_kernel<<<(EE + 255) / 256, 256>>>(dstp);                             // 5
    scan1_kernel<<<NBLK, 256>>>();                                           // 6
    scan2_kernel<<<1, 1024>>>();                                             // 7
    scan3_kernel<<<(NNODE + 255) / 256, 256>>>();                            // 8
    fill_kernel<<<(EE + 255) / 256, 256>>>(src, dstp);                       // 9

    // ----- layer 0 -----
    agg_kernel<<<(NNODE * 32 + 255) / 256, 256>>>(pA, pB);                   // 10
    sage_layer<true><<<(NNODE + 127) / 128, 256, SAGE_SMEM>>>(               // 11
        pB, pA, OFF_V0, v0b, OFF_W0, w0b, pcat, NNODE);

    // ----- layer 1 -----
    agg_kernel<<<(NNODE * 32 + 255) / 256, 256>>>(pcat, pA);                 // 12
    sage_layer<false><<<(NNODE + 127) / 128, 256, SAGE_SMEM>>>(              // 13
        pA, pcat, OFF_V1, v1b, OFF_W1, w1b, (float*)d_out, NNODE);
}

// round 11
// speedup vs baseline: 1.1690x; 1.0204x over previous
#include <cuda_runtime.h>
#include <cuda_bf16.h>
#include <cstdint>

#define NUSR 100000
#define NITM 50000
#define NNODE (NUSR + NITM)
#define DD 128
#define EE 1500000
#define HALFD 64
#define KCAT 320
#define NBLK 586     // ceil(NNODE/256)
#define UBLKS 782    // ceil(NUSR/128)
#define IBLKS 391    // ceil(NITM/128)
#define PROJ_BLKS (UBLKS + IBLKS)
#define EMB_BLKS 18750   // ceil(NNODE*32/256)
#define EDGE_BLKS 5860   // ceil(EE/256)

#define APAD16 20
#define APAD32 36
#define WPAD 136

// weight buffer offsets (floats), plain [k][128] row-major, tf32-rounded
#define OFF_U  0
#define OFF_I  40960
#define OFF_W0 81920
#define OFF_W1 114688
#define OFF_V0 147456
#define OFF_V1 163840
#define WTOT   180224

// -------- scratch (device globals: allocation-free) --------
__device__ float g_bufA[(size_t)NNODE * DD];
__device__ float g_bufB[(size_t)NNODE * DD];
__device__ float g_cat [(size_t)NNODE * KCAT];
__device__ float g_wts [WTOT];
__device__ int   g_deg[NNODE];
__device__ int   g_bsum[1024];
__device__ int   g_offs[NNODE + 1];
__device__ int   g_cursor[NNODE];
__device__ int   g_csr[EE];
__device__ __nv_bfloat16 g_ufeb[5000 * 128];
__device__ __nv_bfloat16 g_ifeb[8000 * 128];
__device__ __nv_bfloat16 g_web [30000 * 64];

// -------- tf32 helpers --------
__device__ __forceinline__ uint32_t f2tf32(float v) {
    uint32_t r;
    asm("cvt.rna.tf32.f32 %0, %1;" : "=r"(r) : "f"(v));
    return r;
}
__device__ __forceinline__ float rtf(float v) { return __uint_as_float(f2tf32(v)); }

__device__ __forceinline__ void mma_tf32(float* c, const uint32_t* a, const uint32_t* b) {
    asm volatile(
        "mma.sync.aligned.m16n8k8.row.col.f32.tf32.tf32.f32 "
        "{%0,%1,%2,%3}, {%4,%5,%6,%7}, {%8,%9}, {%0,%1,%2,%3};"
        : "+f"(c[0]), "+f"(c[1]), "+f"(c[2]), "+f"(c[3])
        : "r"(a[0]), "r"(a[1]), "r"(a[2]), "r"(a[3]), "r"(b[0]), "r"(b[1]));
}

__device__ __forceinline__ void cp16(void* smem_dst, const void* gsrc, bool pred) {
    uint32_t dst = (uint32_t)__cvta_generic_to_shared(smem_dst);
    int sz = pred ? 16 : 0;
    asm volatile("cp.async.ca.shared.global [%0], [%1], 16, %2;\n"
                 :: "r"(dst), "l"(gsrc), "r"(sz));
}
__device__ __forceinline__ void cp_commit() { asm volatile("cp.async.commit_group;\n"); }
__device__ __forceinline__ void cp_wait0()  { asm volatile("cp.async.wait_group 0;\n"); }
__device__ __forceinline__ void cp_wait1()  { asm volatile("cp.async.wait_group 1;\n"); }
__device__ __forceinline__ void cp_wait2()  { asm volatile("cp.async.wait_group 2;\n"); }
__device__ __forceinline__ void cp_wait3()  { asm volatile("cp.async.wait_group 3;\n"); }

// Hs swizzle: row-major [128][128], phys col = col ^ (4*(row&7))
__device__ __forceinline__ int hsw(int r, int c) { return r * 128 + (c ^ ((r & 7) << 2)); }

// ======== prep: conv tables to bf16 + round weights to tf32 + zero deg ========
__global__ void prep_kernel(const float* __restrict__ ufe, const float* __restrict__ ife,
                            const float* __restrict__ we,
                            const float* __restrict__ uW, const float* __restrict__ iW,
                            const float* __restrict__ w0, const float* __restrict__ w1,
                            const float* __restrict__ v0, const float* __restrict__ v1) {
    int i0 = blockIdx.x * blockDim.x + threadIdx.x;
    int st = gridDim.x * blockDim.x;
    for (int i = i0; i < 3584000; i += st) {
        if      (i < 640000)  g_ufeb[i]           = __float2bfloat16(ufe[i]);
        else if (i < 1664000) g_ifeb[i - 640000]  = __float2bfloat16(ife[i - 640000]);
        else                  g_web [i - 1664000] = __float2bfloat16(we [i - 1664000]);
    }
    for (int i = i0; i < WTOT; i += st) {
        float v;
        if      (i < OFF_I)  v = uW[i - OFF_U];
        else if (i < OFF_W0) v = iW[i - OFF_I];
        else if (i < OFF_W1) v = w0[i - OFF_W0];
        else if (i < OFF_V0) v = w1[i - OFF_W1];
        else if (i < OFF_V1) v = v0[i - OFF_V0];
        else                 v = v1[i - OFF_V1];
        g_wts[i] = rtf(v);
    }
    for (int i = i0; i < NNODE; i += st) g_deg[i] = 0;
}

// ======== embed (blocks [0,EMB_BLKS)) + degree count (blocks beyond) ========
__global__ void embed_deg_kernel(const int* __restrict__ uf,  const int* __restrict__ itf,
                                 const int* __restrict__ ut,  const int* __restrict__ it,
                                 const int* __restrict__ dstp) {
    if (blockIdx.x >= EMB_BLKS) {
        int i = (blockIdx.x - EMB_BLKS) * blockDim.x + threadIdx.x;
        if (i < EE) atomicAdd(&g_deg[dstp[i]], 1);
        return;
    }
    int gw   = (blockIdx.x * blockDim.x + threadIdx.x) >> 5;
    int lane = threadIdx.x & 31;
    if (gw >= NNODE) return;
    int n = gw;
    bool user = n < NUSR;
    const int* f = user ? uf + (size_t)n * 10 : itf + (size_t)(n - NUSR) * 10;
    const __nv_bfloat16* tab = user ? g_ufeb : g_ifeb;

    float4 a = make_float4(0.f, 0.f, 0.f, 0.f);
#pragma unroll
    for (int j = 0; j < 10; j++) {
        int r = __ldg(f + j);
        uint2 v = __ldg((const uint2*)(tab + (size_t)r * DD) + lane);
        float2 p0 = __bfloat1622float2(*(__nv_bfloat162*)&v.x);
        float2 p1 = __bfloat1622float2(*(__nv_bfloat162*)&v.y);
        a.x += p0.x; a.y += p0.y; a.z += p1.x; a.w += p1.y;
    }
    float* catrow = g_cat + (size_t)n * KCAT;
    a.x = rtf(a.x * 0.1f); a.y = rtf(a.y * 0.1f);
    a.z = rtf(a.z * 0.1f); a.w = rtf(a.w * 0.1f);
    ((float4*)catrow)[lane] = a;

    const int* t = user ? ut + (size_t)n * 24 : it + (size_t)(n - NUSR) * 24;
#pragma unroll
    for (int fl = 0; fl < 3; fl++) {
        float2 b = make_float2(0.f, 0.f);
#pragma unroll
        for (int w = 0; w < 8; w++) {
            int r = __ldg(t + fl * 8 + w);
            uint32_t v = __ldg((const uint32_t*)(g_web + (size_t)r * HALFD) + lane);
            float2 p = __bfloat1622float2(*(__nv_bfloat162*)&v);
            b.x += p.x; b.y += p.y;
        }
        b.x = rtf(b.x * 0.125f); b.y = rtf(b.y * 0.125f);
        ((float2*)(catrow + 128 + fl * 64))[lane] = b;
    }
}

// -------- scans --------
__global__ void scan1_kernel() {
    __shared__ int sm[256];
    int tid = threadIdx.x;
    int i = blockIdx.x * 256 + tid;
    int v = (i < NNODE) ? g_deg[i] : 0;
    sm[tid] = v;
    __syncthreads();
#pragma unroll
    for (int d = 1; d < 256; d <<= 1) {
        int t = (tid >= d) ? sm[tid - d] : 0;
        __syncthreads();
        sm[tid] += t;
        __syncthreads();
    }
    if (i < NNODE) g_offs[i] = sm[tid] - v;
    if (tid == 255) g_bsum[blockIdx.x] = sm[255];
}

__global__ void scan2_kernel() {
    __shared__ int sm[1024];
    int tid = threadIdx.x;
    int v = (tid < NBLK) ? g_bsum[tid] : 0;
    sm[tid] = v;
    __syncthreads();
#pragma unroll
    for (int d = 1; d < 1024; d <<= 1) {
        int t = (tid >= d) ? sm[tid - d] : 0;
        __syncthreads();
        sm[tid] += t;
        __syncthreads();
    }
    g_bsum[tid] = sm[tid] - v;
}

__global__ void scan3_kernel() {
    int i = blockIdx.x * blockDim.x + threadIdx.x;
    if (i < NNODE) {
        int o = g_offs[i] + g_bsum[i >> 8];
        g_offs[i] = o;
        g_cursor[i] = o;
    }
    if (i == 0) g_offs[NNODE] = EE;
}

// -------- gather aggregation (warp per node), invdeg from CSR offsets --------
__global__ void agg_kernel(const float* __restrict__ x, float* __restrict__ out) {
    int gw   = (blockIdx.x * blockDim.x + threadIdx.x) >> 5;
    int lane = threadIdx.x & 31;
    if (gw >= NNODE) return;
    int off = g_offs[gw];
    int end = g_offs[gw + 1];
    float4 acc = make_float4(0.f, 0.f, 0.f, 0.f);
    for (int j = off; j < end; j++) {
        int s = __ldg(&g_csr[j]);
        float4 v = __ldg((const float4*)(x + (size_t)s * DD) + lane);
        acc.x += v.x; acc.y += v.y; acc.z += v.z; acc.w += v.w;
    }
    float sc = 1.0f / fmaxf((float)(end - off), 1.0f);
    acc.x = rtf(acc.x * sc); acc.y = rtf(acc.y * sc);
    acc.z = rtf(acc.z * sc); acc.w = rtf(acc.w * sc);
    *((float4*)(out + (size_t)gw * DD) + lane) = acc;
}

// ======== merged projection GEMM (blocks [0,PROJ_BLKS)) + CSR fill (beyond) ========
// dyn smem: As[3][128][APAD32] | Ws[2][32][WPAD]
__global__ __launch_bounds__(256) void proj_fill(
    const float* __restrict__ ubias, const float* __restrict__ ibias,
    const float* __restrict__ uid,   const float* __restrict__ iid,
    float* __restrict__ outbase,
    const int* __restrict__ srcp, const int* __restrict__ dstp)
{
    if (blockIdx.x >= PROJ_BLKS) {
        int i = (blockIdx.x - PROJ_BLKS) * blockDim.x + threadIdx.x;
        if (i < EE) {
            int d = dstp[i];
            int pos = atomicAdd(&g_cursor[d], 1);
            g_csr[pos] = srcp[i];
        }
        return;
    }

    extern __shared__ float sm_[];
    float (*As)[128][APAD32] = (float (*)[128][APAD32])sm_;
    float (*Ws)[32][WPAD]    = (float (*)[32][WPAD])(sm_ + 3 * 128 * APAD32);

    bool user = blockIdx.x < UBLKS;
    const float* A      = user ? g_cat : g_cat + (size_t)NUSR * KCAT;
    const float* Wt     = g_wts + (user ? OFF_U : OFF_I);
    const float* bias   = user ? ubias : ibias;
    const float* addmat = user ? uid : iid;
    float* out          = user ? outbase : outbase + (size_t)NUSR * DD;
    int M               = user ? NUSR : NITM;
    int r0              = (user ? blockIdx.x : blockIdx.x - UBLKS) * 128;

    int tid  = threadIdx.x;
    int lane = tid & 31;
    int wid  = tid >> 5;
    int wm = wid & 1, wn = wid >> 1;
    int g  = lane >> 2, tg = lane & 3;

    float acc[4][4][4];
#pragma unroll
    for (int mt = 0; mt < 4; mt++)
#pragma unroll
        for (int nt = 0; nt < 4; nt++)
#pragma unroll
            for (int u = 0; u < 4; u++) acc[mt][nt][u] = 0.f;

    const int T = KCAT / 32;
    auto issueA = [&](int t, int s) {
#pragma unroll
        for (int l = 0; l < 4; l++) {
            int idx = tid + l * 256;
            int m = idx >> 3, c8 = (idx & 7) * 4;
            int row = r0 + m;
            cp16(&As[s][m][c8], A + (size_t)row * KCAT + t * 32 + c8, row < M);
        }
        cp_commit();
    };
    auto issueW = [&](int t, int s) {
#pragma unroll
        for (int l = 0; l < 4; l++) {
            int idx = tid + l * 256;
            int k = idx >> 5, n4 = (idx & 31) * 4;
            cp16(&Ws[s][k][n4], Wt + (size_t)(t * 32 + k) * 128 + n4, true);
        }
        cp_commit();
    };

    issueW(0, 0);
    issueA(0, 0);
    issueA(1, 1);
    for (int t = 0; t < T; t++) {
        int sa = t % 3, sw = t & 1;
        if (t + 1 < T) issueW(t + 1, (t + 1) & 1);
        if (t + 2 < T) issueA(t + 2, (t + 2) % 3);
        if (t + 2 < T) cp_wait3();
        else if (t + 1 < T) cp_wait2();
        else cp_wait0();
        __syncthreads();
#pragma unroll
        for (int ks = 0; ks < 32; ks += 8) {
            uint32_t afr[4][4];
#pragma unroll
            for (int mt = 0; mt < 4; mt++) {
                int rb = wm * 64 + mt * 16 + g;
                afr[mt][0] = __float_as_uint(As[sa][rb    ][ks + tg]);
                afr[mt][1] = __float_as_uint(As[sa][rb + 8][ks + tg]);
                afr[mt][2] = __float_as_uint(As[sa][rb    ][ks + tg + 4]);
                afr[mt][3] = __float_as_uint(As[sa][rb + 8][ks + tg + 4]);
            }
            uint32_t bfr[4][2];
#pragma unroll
            for (int nt = 0; nt < 4; nt++) {
                int cb = wn * 32 + nt * 8 + g;
                bfr[nt][0] = __float_as_uint(Ws[sw][ks + tg    ][cb]);
                bfr[nt][1] = __float_as_uint(Ws[sw][ks + tg + 4][cb]);
            }
#pragma unroll
            for (int mt = 0; mt < 4; mt++)
#pragma unroll
                for (int nt = 0; nt < 4; nt++)
                    mma_tf32(acc[mt][nt], afr[mt], bfr[nt]);
        }
        __syncthreads();
    }

#pragma unroll
    for (int mt = 0; mt < 4; mt++) {
#pragma unroll
        for (int nt = 0; nt < 4; nt++) {
            int col = wn * 32 + nt * 8 + tg * 2;
            int rowa = r0 + wm * 64 + mt * 16 + g;
            int rowb = rowa + 8;
            float b0 = bias[col], b1 = bias[col + 1];
            if (rowa < M) {
                float x0 = rtf(acc[mt][nt][0] + b0 + addmat[(size_t)rowa * 128 + col]);
                float x1 = rtf(acc[mt][nt][1] + b1 + addmat[(size_t)rowa * 128 + col + 1]);
                *(float2*)(out + (size_t)rowa * 128 + col) = make_float2(x0, x1);
            }
            if (rowb < M) {
                float x2 = rtf(acc[mt][nt][2] + b0 + addmat[(size_t)rowb * 128 + col]);
                float x3 = rtf(acc[mt][nt][3] + b1 + addmat[(size_t)rowb * 128 + col + 1]);
                *(float2*)(out + (size_t)rowb * 128 + col) = make_float2(x2, x3);
            }
        }
    }
}

// ======== fused SAGE layer (R6/R10 core): unified 24-tile pipeline ========
// dyn smem: As[3][128][APAD16] | Ws[2][16][WPAD] | Hs[128*128 swizzled]
template <bool RELU>
__global__ __launch_bounds__(256) void sage_layer(
    const float* __restrict__ agg, const float* __restrict__ x,
    int voff, const float* __restrict__ vb,
    int woff, const float* __restrict__ wb,
    float* __restrict__ out, int M)
{
    extern __shared__ float sm_[];
    float (*As)[128][APAD16] = (float (*)[128][APAD16])sm_;
    float (*Ws)[16][WPAD]    = (float (*)[16][WPAD])(sm_ + 3 * 128 * APAD16);
    float* Hs                = sm_ + 3 * 128 * APAD16 + 2 * 16 * WPAD;
    const float* vW = g_wts + voff;
    const float* wW = g_wts + woff;

    int tid  = threadIdx.x;
    int lane = tid & 31;
    int wid  = tid >> 5;
    int wm = wid & 1, wn = wid >> 1;
    int g  = lane >> 2, tg = lane & 3;
    int r0 = blockIdx.x * 128;

    float acc[4][4][4];
#pragma unroll
    for (int mt = 0; mt < 4; mt++)
#pragma unroll
        for (int nt = 0; nt < 4; nt++)
#pragma unroll
            for (int u = 0; u < 4; u++) acc[mt][nt][u] = 0.f;

    auto issueA = [&](int at, int s) {
        const float* Ap = (at < 8) ? agg : x;
        int kt = (at < 8) ? at : at - 8;
#pragma unroll
        for (int l = 0; l < 2; l++) {
            int idx = tid + l * 256;
            int m = idx >> 2, c4 = (idx & 3) * 4;
            int row = r0 + m;
            cp16(&As[s][m][c4], Ap + (size_t)row * DD + kt * 16 + c4, row < M);
        }
        cp_commit();
    };
    auto issueW = [&](int wt, int s) {
        const float* Wp = (wt < 8) ? (vW + (size_t)wt * 2048)
                                   : (wW + (size_t)(wt - 8) * 2048);
#pragma unroll
        for (int l = 0; l < 2; l++) {
            int idx = tid + l * 256;
            int k = idx >> 5, n4 = (idx & 31) * 4;
            cp16(&Ws[s][k][n4], Wp + (size_t)k * 128 + n4, true);
        }
        cp_commit();
    };

    issueW(0, 0);
    issueA(0, 0);
    issueA(1, 1);

    for (int t = 0; t < 24; t++) {
        int sa = t % 3, sw = t & 1;
        if (t + 1 < 24) issueW(t + 1, (t + 1) & 1);
        if (t + 2 < 16) issueA(t + 2, (t + 2) % 3);
        if (t < 14) cp_wait3();
        else if (t == 14) cp_wait2();
        else if (t < 23) cp_wait1();
        else cp_wait0();
        __syncthreads();

        int hc = (t - 16) * 16;
#pragma unroll
        for (int ks = 0; ks < 16; ks += 8) {
            uint32_t afr[4][4];
#pragma unroll
            for (int mt = 0; mt < 4; mt++) {
                int rb = wm * 64 + mt * 16 + g;
                if (t < 16) {
                    afr[mt][0] = __float_as_uint(As[sa][rb    ][ks + tg]);
                    afr[mt][1] = __float_as_uint(As[sa][rb + 8][ks + tg]);
                    afr[mt][2] = __float_as_uint(As[sa][rb    ][ks + tg + 4]);
                    afr[mt][3] = __float_as_uint(As[sa][rb + 8][ks + tg + 4]);
                } else {
                    afr[mt][0] = __float_as_uint(Hs[hsw(rb,     hc + ks + tg)]);
                    afr[mt][1] = __float_as_uint(Hs[hsw(rb + 8, hc + ks + tg)]);
                    afr[mt][2] = __float_as_uint(Hs[hsw(rb,     hc + ks + tg + 4)]);
                    afr[mt][3] = __float_as_uint(Hs[hsw(rb + 8, hc + ks + tg + 4)]);
                }
            }
            uint32_t bfr[4][2];
#pragma unroll
            for (int nt = 0; nt < 4; nt++) {
                int cb = wn * 32 + nt * 8 + g;
                bfr[nt][0] = __float_as_uint(Ws[sw][ks + tg    ][cb]);
                bfr[nt][1] = __float_as_uint(Ws[sw][ks + tg + 4][cb]);
            }
#pragma unroll
            for (int mt = 0; mt < 4; mt++)
#pragma unroll
                for (int nt = 0; nt < 4; nt++)
                    mma_tf32(acc[mt][nt], afr[mt], bfr[nt]);
        }

        if (t == 7) {
#pragma unroll
            for (int mt = 0; mt < 4; mt++) {
#pragma unroll
                for (int nt = 0; nt < 4; nt++) {
                    int col = wn * 32 + nt * 8 + tg * 2;
                    int ra = wm * 64 + mt * 16 + g;
                    float b0 = vb[col], b1 = vb[col + 1];
                    Hs[hsw(ra,     col    )] = rtf(fmaxf(acc[mt][nt][0] + b0, 0.f));
                    Hs[hsw(ra,     col + 1)] = rtf(fmaxf(acc[mt][nt][1] + b1, 0.f));
                    Hs[hsw(ra + 8, col    )] = rtf(fmaxf(acc[mt][nt][2] + b0, 0.f));
                    Hs[hsw(ra + 8, col + 1)] = rtf(fmaxf(acc[mt][nt][3] + b1, 0.f));
#pragma unroll
                    for (int u = 0; u < 4; u++) acc[mt][nt][u] = 0.f;
                }
            }
        }
        __syncthreads();
    }

#pragma unroll
    for (int mt = 0; mt < 4; mt++) {
#pragma unroll
        for (int nt = 0; nt < 4; nt++) {
            int col = wn * 32 + nt * 8 + tg * 2;
            int rowa = r0 + wm * 64 + mt * 16 + g;
            int rowb = rowa + 8;
            float b0 = wb[col], b1 = wb[col + 1];
            if (rowa < M) {
                float x0 = acc[mt][nt][0] + b0;
                float x1 = acc[mt][nt][1] + b1;
                if (RELU) { x0 = rtf(fmaxf(x0, 0.f)); x1 = rtf(fmaxf(x1, 0.f)); }
                *(float2*)(out + (size_t)rowa * 128 + col) = make_float2(x0, x1);
            }
            if (rowb < M) {
                float x2 = acc[mt][nt][2] + b0;
                float x3 = acc[mt][nt][3] + b1;
                if (RELU) { x2 = rtf(fmaxf(x2, 0.f)); x3 = rtf(fmaxf(x3, 0.f)); }
                *(float2*)(out + (size_t)rowb * 128 + col) = make_float2(x2, x3);
            }
        }
    }
}

// -------- launch --------
extern "C" void kernel_launch(void* const* d_in, const int* in_sizes, int n_in,
                              void* d_out, int out_size) {
    const int*   edge          = (const int*)d_in[0];
    const int*   src           = edge;
    const int*   dstp          = edge + EE;
    const int*   user_features = (const int*)d_in[1];
    const int*   item_features = (const int*)d_in[2];
    const int*   user_text     = (const int*)d_in[3];
    const int*   item_text     = (const int*)d_in[4];
    const float* user_id_emb   = (const float*)d_in[5];
    const float* item_id_emb   = (const float*)d_in[6];
    const float* user_feat_emb = (const float*)d_in[7];
    const float* item_feat_emb = (const float*)d_in[8];
    const float* word_emb      = (const float*)d_in[9];
    const float* user_projW    = (const float*)d_in[10];
    const float* user_projb    = (const float*)d_in[11];
    const float* item_projW    = (const float*)d_in[12];
    const float* item_projb    = (const float*)d_in[13];
    const float* w0W = (const float*)d_in[14];
    const float* w0b = (const float*)d_in[15];
    const float* w1W = (const float*)d_in[16];
    const float* w1b = (const float*)d_in[17];
    const float* v0W = (const float*)d_in[18];
    const float* v0b = (const float*)d_in[19];
    const float* v1W = (const float*)d_in[20];
    const float* v1b = (const float*)d_in[21];

    float *pA, *pB, *pcat;
    cudaGetSymbolAddress((void**)&pA,   g_bufA);
    cudaGetSymbolAddress((void**)&pB,   g_bufB);
    cudaGetSymbolAddress((void**)&pcat, g_cat);

    const int GEMM_SMEM = (3 * 128 * APAD32 + 2 * 32 * WPAD) * 4;               // 90112
    const int SAGE_SMEM = (3 * 128 * APAD16 + 2 * 16 * WPAD + 128 * 128) * 4;   // 113152
    cudaFuncSetAttribute(proj_fill, cudaFuncAttributeMaxDynamicSharedMemorySize, GEMM_SMEM);
    cudaFuncSetAttribute(sage_layer<true>,  cudaFuncAttributeMaxDynamicSharedMemorySize, SAGE_SMEM);
    cudaFuncSetAttribute(sage_layer<false>, cudaFuncAttributeMaxDynamicSharedMemorySize, SAGE_SMEM);

    // 0: tables->bf16, weights->tf32, zero deg
    prep_kernel<<<2048, 256>>>(user_feat_emb, item_feat_emb, word_emb,
                               user_projW, item_projW, w0W, w1W, v0W, v1W);
    // 1: embed (+ deg counting riding along)
    embed_deg_kernel<<<EMB_BLKS + EDGE_BLKS, 256>>>(
        user_features, item_features, user_text, item_text, dstp);
    // 2-4: exclusive scan of degrees -> offsets/cursor
    scan1_kernel<<<NBLK, 256>>>();
    scan2_kernel<<<1, 1024>>>();
    scan3_kernel<<<(NNODE + 255) / 256, 256>>>();
    // 5: projection GEMM (+ CSR fill riding along)
    proj_fill<<<PROJ_BLKS + EDGE_BLKS, 256, GEMM_SMEM>>>(
        user_projb, item_projb, user_id_emb, item_id_emb, pA, src, dstp);

    // ----- layer 0 -----
    agg_kernel<<<(NNODE * 32 + 255) / 256, 256>>>(pA, pB);
    sage_layer<true><<<(NNODE + 127) / 128, 256, SAGE_SMEM>>>(
        pB, pA, OFF_V0, v0b, OFF_W0, w0b, pcat, NNODE);

    // ----- layer 1 -----
    agg_kernel<<<(NNODE * 32 + 255) / 256, 256>>>(pcat, pA);
    sage_layer<false><<<(NNODE + 127) / 128, 256, SAGE_SMEM>>>(
        pA, pcat, OFF_V1, v1b, OFF_W1, w1b, (float*)d_out, NNODE);
}

// round 13
// speedup vs baseline: 1.1862x; 1.0147x over previous
#include <cuda_runtime.h>
#include <cuda_bf16.h>
#include <cuda_fp16.h>
#include <cstdint>

#define NUSR 100000
#define NITM 50000
#define NNODE (NUSR + NITM)
#define DD 128
#define EE 1500000
#define HALFD 64
#define KCAT 320
#define NBLK 586     // ceil(NNODE/256)
#define UBLKS 782    // ceil(NUSR/128)
#define IBLKS 391    // ceil(NITM/128)
#define PROJ_BLKS (UBLKS + IBLKS)
#define EMB_BLKS 18750   // ceil(NNODE*32/256)
#define EDGE_BLKS 5860   // ceil(EE/256)

#define APAD16 20
#define APAD32 36
#define WPAD 136

// weight buffer offsets (floats), plain [k][128] row-major, tf32-rounded
#define OFF_U  0
#define OFF_I  40960
#define OFF_W0 81920
#define OFF_W1 114688
#define OFF_V0 147456
#define OFF_V1 163840
#define WTOT   180224

// -------- scratch (device globals: allocation-free) --------
__device__ float  g_bufA[(size_t)NNODE * DD];
__device__ float  g_bufB[(size_t)NNODE * DD];
__device__ float  g_cat [(size_t)NNODE * KCAT];
__device__ __half g_x16 [(size_t)NNODE * DD];   // fp16 mirror of x for agg gathers
__device__ float  g_wts [WTOT];
__device__ int    g_deg[NNODE];
__device__ int    g_bsum[1024];
__device__ int    g_offs[NNODE + 1];
__device__ int    g_cursor[NNODE];
__device__ int    g_csr[EE];
__device__ __nv_bfloat16 g_ufeb[5000 * 128];
__device__ __nv_bfloat16 g_ifeb[8000 * 128];
__device__ __nv_bfloat16 g_web [30000 * 64];

// -------- tf32 helpers --------
__device__ __forceinline__ uint32_t f2tf32(float v) {
    uint32_t r;
    asm("cvt.rna.tf32.f32 %0, %1;" : "=r"(r) : "f"(v));
    return r;
}
__device__ __forceinline__ float rtf(float v) { return __uint_as_float(f2tf32(v)); }

__device__ __forceinline__ void mma_tf32(float* c, const uint32_t* a, const uint32_t* b) {
    asm volatile(
        "mma.sync.aligned.m16n8k8.row.col.f32.tf32.tf32.f32 "
        "{%0,%1,%2,%3}, {%4,%5,%6,%7}, {%8,%9}, {%0,%1,%2,%3};"
        : "+f"(c[0]), "+f"(c[1]), "+f"(c[2]), "+f"(c[3])
        : "r"(a[0]), "r"(a[1]), "r"(a[2]), "r"(a[3]), "r"(b[0]), "r"(b[1]));
}

__device__ __forceinline__ void cp16(void* smem_dst, const void* gsrc, bool pred) {
    uint32_t dst = (uint32_t)__cvta_generic_to_shared(smem_dst);
    int sz = pred ? 16 : 0;
    asm volatile("cp.async.ca.shared.global [%0], [%1], 16, %2;\n"
                 :: "r"(dst), "l"(gsrc), "r"(sz));
}
__device__ __forceinline__ void cp_commit() { asm volatile("cp.async.commit_group;\n"); }
__device__ __forceinline__ void cp_wait0()  { asm volatile("cp.async.wait_group 0;\n"); }
__device__ __forceinline__ void cp_wait1()  { asm volatile("cp.async.wait_group 1;\n"); }
__device__ __forceinline__ void cp_wait2()  { asm volatile("cp.async.wait_group 2;\n"); }
__device__ __forceinline__ void cp_wait3()  { asm volatile("cp.async.wait_group 3;\n"); }

// Hs swizzle: row-major [128][128], phys col = col ^ (4*(row&7))
__device__ __forceinline__ int hsw(int r, int c) { return r * 128 + (c ^ ((r & 7) << 2)); }

// ======== prep: conv tables to bf16 + round weights to tf32 + zero deg ========
__global__ void prep_kernel(const float* __restrict__ ufe, const float* __restrict__ ife,
                            const float* __restrict__ we,
                            const float* __restrict__ uW, const float* __restrict__ iW,
                            const float* __restrict__ w0, const float* __restrict__ w1,
                            const float* __restrict__ v0, const float* __restrict__ v1) {
    int i0 = blockIdx.x * blockDim.x + threadIdx.x;
    int st = gridDim.x * blockDim.x;
    for (int i = i0; i < 3584000; i += st) {
        if      (i < 640000)  g_ufeb[i]           = __float2bfloat16(ufe[i]);
        else if (i < 1664000) g_ifeb[i - 640000]  = __float2bfloat16(ife[i - 640000]);
        else                  g_web [i - 1664000] = __float2bfloat16(we [i - 1664000]);
    }
    for (int i = i0; i < WTOT; i += st) {
        float v;
        if      (i < OFF_I)  v = uW[i - OFF_U];
        else if (i < OFF_W0) v = iW[i - OFF_I];
        else if (i < OFF_W1) v = w0[i - OFF_W0];
        else if (i < OFF_V0) v = w1[i - OFF_W1];
        else if (i < OFF_V1) v = v0[i - OFF_V0];
        else                 v = v1[i - OFF_V1];
        g_wts[i] = rtf(v);
    }
    for (int i = i0; i < NNODE; i += st) g_deg[i] = 0;
}

// ======== embed (blocks [0,EMB_BLKS)) + degree count (blocks beyond) ========
__global__ void embed_deg_kernel(const int* __restrict__ uf,  const int* __restrict__ itf,
                                 const int* __restrict__ ut,  const int* __restrict__ it,
                                 const int* __restrict__ dstp) {
    if (blockIdx.x >= EMB_BLKS) {
        int i = (blockIdx.x - EMB_BLKS) * blockDim.x + threadIdx.x;
        if (i < EE) atomicAdd(&g_deg[dstp[i]], 1);
        return;
    }
    int gw   = (blockIdx.x * blockDim.x + threadIdx.x) >> 5;
    int lane = threadIdx.x & 31;
    if (gw >= NNODE) return;
    int n = gw;
    bool user = n < NUSR;
    const int* f = user ? uf + (size_t)n * 10 : itf + (size_t)(n - NUSR) * 10;
    const __nv_bfloat16* tab = user ? g_ufeb : g_ifeb;

    float4 a = make_float4(0.f, 0.f, 0.f, 0.f);
#pragma unroll
    for (int j = 0; j < 10; j++) {
        int r = __ldg(f + j);
        uint2 v = __ldg((const uint2*)(tab + (size_t)r * DD) + lane);
        float2 p0 = __bfloat1622float2(*(__nv_bfloat162*)&v.x);
        float2 p1 = __bfloat1622float2(*(__nv_bfloat162*)&v.y);
        a.x += p0.x; a.y += p0.y; a.z += p1.x; a.w += p1.y;
    }
    float* catrow = g_cat + (size_t)n * KCAT;
    a.x = rtf(a.x * 0.1f); a.y = rtf(a.y * 0.1f);
    a.z = rtf(a.z * 0.1f); a.w = rtf(a.w * 0.1f);
    ((float4*)catrow)[lane] = a;

    const int* t = user ? ut + (size_t)n * 24 : it + (size_t)(n - NUSR) * 24;
#pragma unroll
    for (int fl = 0; fl < 3; fl++) {
        float2 b = make_float2(0.f, 0.f);
#pragma unroll
        for (int w = 0; w < 8; w++) {
            int r = __ldg(t + fl * 8 + w);
            uint32_t v = __ldg((const uint32_t*)(g_web + (size_t)r * HALFD) + lane);
            float2 p = __bfloat1622float2(*(__nv_bfloat162*)&v);
            b.x += p.x; b.y += p.y;
        }
        b.x = rtf(b.x * 0.125f); b.y = rtf(b.y * 0.125f);
        ((float2*)(catrow + 128 + fl * 64))[lane] = b;
    }
}

// -------- scans --------
__global__ void scan1_kernel() {
    __shared__ int sm[256];
    int tid = threadIdx.x;
    int i = blockIdx.x * 256 + tid;
    int v = (i < NNODE) ? g_deg[i] : 0;
    sm[tid] = v;
    __syncthreads();
#pragma unroll
    for (int d = 1; d < 256; d <<= 1) {
        int t = (tid >= d) ? sm[tid - d] : 0;
        __syncthreads();
        sm[tid] += t;
        __syncthreads();
    }
    if (i < NNODE) g_offs[i] = sm[tid] - v;
    if (tid == 255) g_bsum[blockIdx.x] = sm[255];
}

__global__ void scan2_kernel() {
    __shared__ int sm[1024];
    int tid = threadIdx.x;
    int v = (tid < NBLK) ? g_bsum[tid] : 0;
    sm[tid] = v;
    __syncthreads();
#pragma unroll
    for (int d = 1; d < 1024; d <<= 1) {
        int t = (tid >= d) ? sm[tid - d] : 0;
        __syncthreads();
        sm[tid] += t;
        __syncthreads();
    }
    g_bsum[tid] = sm[tid] - v;
}

__global__ void scan3_kernel() {
    int i = blockIdx.x * blockDim.x + threadIdx.x;
    if (i < NNODE) {
        int o = g_offs[i] + g_bsum[i >> 8];
        g_offs[i] = o;
        g_cursor[i] = o;
    }
    if (i == 0) g_offs[NNODE] = EE;
}

// -------- gather aggregation from fp16 mirror (warp per node) --------
__global__ void agg_kernel(float* __restrict__ out) {
    int gw   = (blockIdx.x * blockDim.x + threadIdx.x) >> 5;
    int lane = threadIdx.x & 31;
    if (gw >= NNODE) return;
    int off = g_offs[gw];
    int end = g_offs[gw + 1];
    float4 acc = make_float4(0.f, 0.f, 0.f, 0.f);
    for (int j = off; j < end; j++) {
        int s = __ldg(&g_csr[j]);
        uint2 v = __ldg((const uint2*)(g_x16 + (size_t)s * DD) + lane);
        float2 p0 = __half22float2(*(__half2*)&v.x);
        float2 p1 = __half22float2(*(__half2*)&v.y);
        acc.x += p0.x; acc.y += p0.y; acc.z += p1.x; acc.w += p1.y;
    }
    float sc = 1.0f / fmaxf((float)(end - off), 1.0f);
    acc.x = rtf(acc.x * sc); acc.y = rtf(acc.y * sc);
    acc.z = rtf(acc.z * sc); acc.w = rtf(acc.w * sc);
    *((float4*)(out + (size_t)gw * DD) + lane) = acc;
}

// ======== merged projection GEMM (blocks [0,PROJ_BLKS)) + CSR fill (beyond) ========
// dyn smem: As[3][128][APAD32] | Ws[2][32][WPAD] ; epilogue also writes fp16 mirror
__global__ __launch_bounds__(256) void proj_fill(
    const float* __restrict__ ubias, const float* __restrict__ ibias,
    const float* __restrict__ uid,   const float* __restrict__ iid,
    float* __restrict__ outbase,
    const int* __restrict__ srcp, const int* __restrict__ dstp)
{
    if (blockIdx.x >= PROJ_BLKS) {
        int i = (blockIdx.x - PROJ_BLKS) * blockDim.x + threadIdx.x;
        if (i < EE) {
            int d = dstp[i];
            int pos = atomicAdd(&g_cursor[d], 1);
            g_csr[pos] = srcp[i];
        }
        return;
    }

    extern __shared__ float sm_[];
    float (*As)[128][APAD32] = (float (*)[128][APAD32])sm_;
    float (*Ws)[32][WPAD]    = (float (*)[32][WPAD])(sm_ + 3 * 128 * APAD32);

    bool user = blockIdx.x < UBLKS;
    const float* A      = user ? g_cat : g_cat + (size_t)NUSR * KCAT;
    const float* Wt     = g_wts + (user ? OFF_U : OFF_I);
    const float* bias   = user ? ubias : ibias;
    const float* addmat = user ? uid : iid;
    float* out          = user ? outbase : outbase + (size_t)NUSR * DD;
    __half* mir         = user ? g_x16 : g_x16 + (size_t)NUSR * DD;
    int M               = user ? NUSR : NITM;
    int r0              = (user ? blockIdx.x : blockIdx.x - UBLKS) * 128;

    int tid  = threadIdx.x;
    int lane = tid & 31;
    int wid  = tid >> 5;
    int wm = wid & 1, wn = wid >> 1;
    int g  = lane >> 2, tg = lane & 3;

    float acc[4][4][4];
#pragma unroll
    for (int mt = 0; mt < 4; mt++)
#pragma unroll
        for (int nt = 0; nt < 4; nt++)
#pragma unroll
            for (int u = 0; u < 4; u++) acc[mt][nt][u] = 0.f;

    const int T = KCAT / 32;
    auto issueA = [&](int t, int s) {
#pragma unroll
        for (int l = 0; l < 4; l++) {
            int idx = tid + l * 256;
            int m = idx >> 3, c8 = (idx & 7) * 4;
            int row = r0 + m;
            cp16(&As[s][m][c8], A + (size_t)row * KCAT + t * 32 + c8, row < M);
        }
        cp_commit();
    };
    auto issueW = [&](int t, int s) {
#pragma unroll
        for (int l = 0; l < 4; l++) {
            int idx = tid + l * 256;
            int k = idx >> 5, n4 = (idx & 31) * 4;
            cp16(&Ws[s][k][n4], Wt + (size_t)(t * 32 + k) * 128 + n4, true);
        }
        cp_commit();
    };

    issueW(0, 0);
    issueA(0, 0);
    issueA(1, 1);
    for (int t = 0; t < T; t++) {
        int sa = t % 3, sw = t & 1;
        if (t + 1 < T) issueW(t + 1, (t + 1) & 1);
        if (t + 2 < T) issueA(t + 2, (t + 2) % 3);
        if (t + 2 < T) cp_wait3();
        else if (t + 1 < T) cp_wait2();
        else cp_wait0();
        __syncthreads();
#pragma unroll
        for (int ks = 0; ks < 32; ks += 8) {
            uint32_t afr[4][4];
#pragma unroll
            for (int mt = 0; mt < 4; mt++) {
                int rb = wm * 64 + mt * 16 + g;
                afr[mt][0] = __float_as_uint(As[sa][rb    ][ks + tg]);
                afr[mt][1] = __float_as_uint(As[sa][rb + 8][ks + tg]);
                afr[mt][2] = __float_as_uint(As[sa][rb    ][ks + tg + 4]);
                afr[mt][3] = __float_as_uint(As[sa][rb + 8][ks + tg + 4]);
            }
            uint32_t bfr[4][2];
#pragma unroll
            for (int nt = 0; nt < 4; nt++) {
                int cb = wn * 32 + nt * 8 + g;
                bfr[nt][0] = __float_as_uint(Ws[sw][ks + tg    ][cb]);
                bfr[nt][1] = __float_as_uint(Ws[sw][ks + tg + 4][cb]);
            }
#pragma unroll
            for (int mt = 0; mt < 4; mt++)
#pragma unroll
                for (int nt = 0; nt < 4; nt++)
                    mma_tf32(acc[mt][nt], afr[mt], bfr[nt]);
        }
        __syncthreads();
    }

#pragma unroll
    for (int mt = 0; mt < 4; mt++) {
#pragma unroll
        for (int nt = 0; nt < 4; nt++) {
            int col = wn * 32 + nt * 8 + tg * 2;
            int rowa = r0 + wm * 64 + mt * 16 + g;
            int rowb = rowa + 8;
            float b0 = bias[col], b1 = bias[col + 1];
            if (rowa < M) {
                float x0 = rtf(acc[mt][nt][0] + b0 + addmat[(size_t)rowa * 128 + col]);
                float x1 = rtf(acc[mt][nt][1] + b1 + addmat[(size_t)rowa * 128 + col + 1]);
                *(float2*)(out + (size_t)rowa * 128 + col) = make_float2(x0, x1);
                *(__half2*)(mir + (size_t)rowa * 128 + col) = __floats2half2_rn(x0, x1);
            }
            if (rowb < M) {
                float x2 = rtf(acc[mt][nt][2] + b0 + addmat[(size_t)rowb * 128 + col]);
                float x3 = rtf(acc[mt][nt][3] + b1 + addmat[(size_t)rowb * 128 + col + 1]);
                *(float2*)(out + (size_t)rowb * 128 + col) = make_float2(x2, x3);
                *(__half2*)(mir + (size_t)rowb * 128 + col) = __floats2half2_rn(x2, x3);
            }
        }
    }
}

// ======== fused SAGE layer (proven core): unified 24-tile pipeline ========
// dyn smem: As[3][128][APAD16] | Ws[2][16][WPAD] | Hs[128*128 swizzled]
// MIRROR: also write fp16 mirror of the output (needed when another agg follows)
template <bool RELU, bool MIRROR>
__global__ __launch_bounds__(256) void sage_layer(
    const float* __restrict__ agg, const float* __restrict__ x,
    int voff, const float* __restrict__ vb,
    int woff, const float* __restrict__ wb,
    float* __restrict__ out, int M)
{
    extern __shared__ float sm_[];
    float (*As)[128][APAD16] = (float (*)[128][APAD16])sm_;
    float (*Ws)[16][WPAD]    = (float (*)[16][WPAD])(sm_ + 3 * 128 * APAD16);
    float* Hs                = sm_ + 3 * 128 * APAD16 + 2 * 16 * WPAD;
    const float* vW = g_wts + voff;
    const float* wW = g_wts + woff;

    int tid  = threadIdx.x;
    int lane = tid & 31;
    int wid  = tid >> 5;
    int wm = wid & 1, wn = wid >> 1;
    int g  = lane >> 2, tg = lane & 3;
    int r0 = blockIdx.x * 128;

    float acc[4][4][4];
#pragma unroll
    for (int mt = 0; mt < 4; mt++)
#pragma unroll
        for (int nt = 0; nt < 4; nt++)
#pragma unroll
            for (int u = 0; u < 4; u++) acc[mt][nt][u] = 0.f;

    auto issueA = [&](int at, int s) {
        const float* Ap = (at < 8) ? agg : x;
        int kt = (at < 8) ? at : at - 8;
#pragma unroll
        for (int l = 0; l < 2; l++) {
            int idx = tid + l * 256;
            int m = idx >> 2, c4 = (idx & 3) * 4;
            int row = r0 + m;
            cp16(&As[s][m][c4], Ap + (size_t)row * DD + kt * 16 + c4, row < M);
        }
        cp_commit();
    };
    auto issueW = [&](int wt, int s) {
        const float* Wp = (wt < 8) ? (vW + (size_t)wt * 2048)
                                   : (wW + (size_t)(wt - 8) * 2048);
#pragma unroll
        for (int l = 0; l < 2; l++) {
            int idx = tid + l * 256;
            int k = idx >> 5, n4 = (idx & 31) * 4;
            cp16(&Ws[s][k][n4], Wp + (size_t)k * 128 + n4, true);
        }
        cp_commit();
    };

    issueW(0, 0);
    issueA(0, 0);
    issueA(1, 1);

    for (int t = 0; t < 24; t++) {
        int sa = t % 3, sw = t & 1;
        if (t + 1 < 24) issueW(t + 1, (t + 1) & 1);
        if (t + 2 < 16) issueA(t + 2, (t + 2) % 3);
        if (t < 14) cp_wait3();
        else if (t == 14) cp_wait2();
        else if (t < 23) cp_wait1();
        else cp_wait0();
        __syncthreads();

        int hc = (t - 16) * 16;
#pragma unroll
        for (int ks = 0; ks < 16; ks += 8) {
            uint32_t afr[4][4];
#pragma unroll
            for (int mt = 0; mt < 4; mt++) {
                int rb = wm * 64 + mt * 16 + g;
                if (t < 16) {
                    afr[mt][0] = __float_as_uint(As[sa][rb    ][ks + tg]);
                    afr[mt][1] = __float_as_uint(As[sa][rb + 8][ks + tg]);
                    afr[mt][2] = __float_as_uint(As[sa][rb    ][ks + tg + 4]);
                    afr[mt][3] = __float_as_uint(As[sa][rb + 8][ks + tg + 4]);
                } else {
                    afr[mt][0] = __float_as_uint(Hs[hsw(rb,     hc + ks + tg)]);
                    afr[mt][1] = __float_as_uint(Hs[hsw(rb + 8, hc + ks + tg)]);
                    afr[mt][2] = __float_as_uint(Hs[hsw(rb,     hc + ks + tg + 4)]);
                    afr[mt][3] = __float_as_uint(Hs[hsw(rb + 8, hc + ks + tg + 4)]);
                }
            }
            uint32_t bfr[4][2];
#pragma unroll
            for (int nt = 0; nt < 4; nt++) {
                int cb = wn * 32 + nt * 8 + g;
                bfr[nt][0] = __float_as_uint(Ws[sw][ks + tg    ][cb]);
                bfr[nt][1] = __float_as_uint(Ws[sw][ks + tg + 4][cb]);
            }
#pragma unroll
            for (int mt = 0; mt < 4; mt++)
#pragma unroll
                for (int nt = 0; nt < 4; nt++)
                    mma_tf32(acc[mt][nt], afr[mt], bfr[nt]);
        }

        if (t == 7) {
#pragma unroll
            for (int mt = 0; mt < 4; mt++) {
#pragma unroll
                for (int nt = 0; nt < 4; nt++) {
                    int col = wn * 32 + nt * 8 + tg * 2;
                    int ra = wm * 64 + mt * 16 + g;
                    float b0 = vb[col], b1 = vb[col + 1];
                    Hs[hsw(ra,     col    )] = rtf(fmaxf(acc[mt][nt][0] + b0, 0.f));
                    Hs[hsw(ra,     col + 1)] = rtf(fmaxf(acc[mt][nt][1] + b1, 0.f));
                    Hs[hsw(ra + 8, col    )] = rtf(fmaxf(acc[mt][nt][2] + b0, 0.f));
                    Hs[hsw(ra + 8, col + 1)] = rtf(fmaxf(acc[mt][nt][3] + b1, 0.f));
#pragma unroll
                    for (int u = 0; u < 4; u++) acc[mt][nt][u] = 0.f;
                }
            }
        }
        __syncthreads();
    }

#pragma unroll
    for (int mt = 0; mt < 4; mt++) {
#pragma unroll
        for (int nt = 0; nt < 4; nt++) {
            int col = wn * 32 + nt * 8 + tg * 2;
            int rowa = r0 + wm * 64 + mt * 16 + g;
            int rowb = rowa + 8;
            float b0 = wb[col], b1 = wb[col + 1];
            if (rowa < M) {
                float x0 = acc[mt][nt][0] + b0;
                float x1 = acc[mt][nt][1] + b1;
                if (RELU) { x0 = rtf(fmaxf(x0, 0.f)); x1 = rtf(fmaxf(x1, 0.f)); }
                *(float2*)(out + (size_t)rowa * 128 + col) = make_float2(x0, x1);
                if (MIRROR)
                    *(__half2*)(g_x16 + (size_t)rowa * 128 + col) = __floats2half2_rn(x0, x1);
            }
            if (rowb < M) {
                float x2 = acc[mt][nt][2] + b0;
                float x3 = acc[mt][nt][3] + b1;
                if (RELU) { x2 = rtf(fmaxf(x2, 0.f)); x3 = rtf(fmaxf(x3, 0.f)); }
                *(float2*)(out + (size_t)rowb * 128 + col) = make_float2(x2, x3);
                if (MIRROR)
                    *(__half2*)(g_x16 + (size_t)rowb * 128 + col) = __floats2half2_rn(x2, x3);
            }
        }
    }
}

// -------- launch --------
extern "C" void kernel_launch(void* const* d_in, const int* in_sizes, int n_in,
                              void* d_out, int out_size) {
    const int*   edge          = (const int*)d_in[0];
    const int*   src           = edge;
    const int*   dstp          = edge + EE;
    const int*   user_features = (const int*)d_in[1];
    const int*   item_features = (const int*)d_in[2];
    const int*   user_text     = (const int*)d_in[3];
    const int*   item_text     = (const int*)d_in[4];
    const float* user_id_emb   = (const float*)d_in[5];
    const float* item_id_emb   = (const float*)d_in[6];
    const float* user_feat_emb = (const float*)d_in[7];
    const float* item_feat_emb = (const float*)d_in[8];
    const float* word_emb      = (const float*)d_in[9];
    const float* user_projW    = (const float*)d_in[10];
    const float* user_projb    = (const float*)d_in[11];
    const float* item_projW    = (const float*)d_in[12];
    const float* item_projb    = (const float*)d_in[13];
    const float* w0W = (const float*)d_in[14];
    const float* w0b = (const float*)d_in[15];
    const float* w1W = (const float*)d_in[16];
    const float* w1b = (const float*)d_in[17];
    const float* v0W = (const float*)d_in[18];
    const float* v0b = (const float*)d_in[19];
    const float* v1W = (const float*)d_in[20];
    const float* v1b = (const float*)d_in[21];

    float *pA, *pB, *pcat;
    cudaGetSymbolAddress((void**)&pA,   g_bufA);
    cudaGetSymbolAddress((void**)&pB,   g_bufB);
    cudaGetSymbolAddress((void**)&pcat, g_cat);

    const int GEMM_SMEM = (3 * 128 * APAD32 + 2 * 32 * WPAD) * 4;               // 90112
    const int SAGE_SMEM = (3 * 128 * APAD16 + 2 * 16 * WPAD + 128 * 128) * 4;   // 113152
    cudaFuncSetAttribute(proj_fill, cudaFuncAttributeMaxDynamicSharedMemorySize, GEMM_SMEM);
    cudaFuncSetAttribute(sage_layer<true, true>,   cudaFuncAttributeMaxDynamicSharedMemorySize, SAGE_SMEM);
    cudaFuncSetAttribute(sage_layer<false, false>, cudaFuncAttributeMaxDynamicSharedMemorySize, SAGE_SMEM);

    // 0: tables->bf16, weights->tf32, zero deg
    prep_kernel<<<2048, 256>>>(user_feat_emb, item_feat_emb, word_emb,
                               user_projW, item_projW, w0W, w1W, v0W, v1W);
    // 1: embed (+ deg counting riding along)
    embed_deg_kernel<<<EMB_BLKS + EDGE_BLKS, 256>>>(
        user_features, item_features, user_text, item_text, dstp);
    // 2-4: exclusive scan of degrees -> offsets/cursor
    scan1_kernel<<<NBLK, 256>>>();
    scan2_kernel<<<1, 1024>>>();
    scan3_kernel<<<(NNODE + 255) / 256, 256>>>();
    // 5: projection GEMM (+ CSR fill riding along); writes x fp32 + fp16 mirror
    proj_fill<<<PROJ_BLKS + EDGE_BLKS, 256, GEMM_SMEM>>>(
        user_projb, item_projb, user_id_emb, item_id_emb, pA, src, dstp);

    // ----- layer 0 -----
    agg_kernel<<<(NNODE * 32 + 255) / 256, 256>>>(pB);          // gathers fp16 mirror
    sage_layer<true, true><<<(NNODE + 127) / 128, 256, SAGE_SMEM>>>(
        pB, pA, OFF_V0, v0b, OFF_W0, w0b, pcat, NNODE);         // writes pcat + mirror

    // ----- layer 1 -----
    agg_kernel<<<(NNODE * 32 + 255) / 256, 256>>>(pA);          // gathers fp16 mirror
    sage_layer<false, false><<<(NNODE + 127) / 128, 256, SAGE_SMEM>>>(
        pA, pcat, OFF_V1, v1b, OFF_W1, w1b, (float*)d_out, NNODE);
}

// round 14
// speedup vs baseline: 1.3994x; 1.1797x over previous
#include <cuda_runtime.h>
#include <cuda_bf16.h>
#include <cuda_fp16.h>
#include <cstdint>

#define NUSR 100000
#define NITM 50000
#define NNODE (NUSR + NITM)
#define DD 128
#define EE 1500000
#define HALFD 64
#define KCAT 320
#define NBLK 586     // ceil(NNODE/256)
#define UBLKS 782    // ceil(NUSR/128)
#define IBLKS 391    // ceil(NITM/128)
#define PROJ_BLKS (UBLKS + IBLKS)
#define EMB_BLKS 18750   // ceil(NNODE*32/256)
#define EDGE_BLKS 5860   // ceil(EE/256)

// fp16 weight buffer offsets (halves), transposed [n][K] per matrix
#define OFF_U  0
#define OFF_I  40960
#define OFF_W0 81920
#define OFF_W1 114688
#define OFF_V0 147456
#define OFF_V1 163840
#define WTOT   180224

// smem strides (halves) — conflict-free for half2 fragment loads
#define PSTR 40   // proj tiles: 32 data + 8 pad   (20 words: 20g+tg distinct mod 32)
#define SSTR 24   // sage tiles: 16 data + 8 pad   (12 words: 12g+tg distinct mod 32)

// -------- scratch (device globals: allocation-free) --------
__device__ __half g_cat16[(size_t)NNODE * KCAT];
__device__ __half g_x16  [(size_t)NNODE * DD];
__device__ __half g_agg16[(size_t)NNODE * DD];
__device__ __half g_wth  [WTOT];
__device__ int    g_deg[NNODE];
__device__ int    g_bsum[1024];
__device__ int    g_offs[NNODE + 1];
__device__ int    g_cursor[NNODE];
__device__ int    g_csr[EE];
__device__ __nv_bfloat16 g_ufeb[5000 * 128];
__device__ __nv_bfloat16 g_ifeb[8000 * 128];
__device__ __nv_bfloat16 g_web [30000 * 64];

// -------- fp16 mma helper: m16n8k16, fp32 accumulate --------
__device__ __forceinline__ void mma_f16(float* c, const uint32_t* a, const uint32_t* b) {
    asm volatile(
        "mma.sync.aligned.m16n8k16.row.col.f32.f16.f16.f32 "
        "{%0,%1,%2,%3}, {%4,%5,%6,%7}, {%8,%9}, {%0,%1,%2,%3};"
        : "+f"(c[0]), "+f"(c[1]), "+f"(c[2]), "+f"(c[3])
        : "r"(a[0]), "r"(a[1]), "r"(a[2]), "r"(a[3]), "r"(b[0]), "r"(b[1]));
}

__device__ __forceinline__ void cp16(void* smem_dst, const void* gsrc, bool pred) {
    uint32_t dst = (uint32_t)__cvta_generic_to_shared(smem_dst);
    int sz = pred ? 16 : 0;
    asm volatile("cp.async.ca.shared.global [%0], [%1], 16, %2;\n"
                 :: "r"(dst), "l"(gsrc), "r"(sz));
}
__device__ __forceinline__ void cp_commit() { asm volatile("cp.async.commit_group;\n"); }
__device__ __forceinline__ void cp_wait0()  { asm volatile("cp.async.wait_group 0;\n"); }
__device__ __forceinline__ void cp_wait1()  { asm volatile("cp.async.wait_group 1;\n"); }
__device__ __forceinline__ void cp_wait2()  { asm volatile("cp.async.wait_group 2;\n"); }
__device__ __forceinline__ void cp_wait3()  { asm volatile("cp.async.wait_group 3;\n"); }

// ======== prep: tables->bf16, weights->fp16 transposed [n][K], zero deg ========
__global__ void prep_kernel(const float* __restrict__ ufe, const float* __restrict__ ife,
                            const float* __restrict__ we,
                            const float* __restrict__ uW, const float* __restrict__ iW,
                            const float* __restrict__ w0, const float* __restrict__ w1,
                            const float* __restrict__ v0, const float* __restrict__ v1) {
    int i0 = blockIdx.x * blockDim.x + threadIdx.x;
    int st = gridDim.x * blockDim.x;
    for (int i = i0; i < 3584000; i += st) {
        if      (i < 640000)  g_ufeb[i]           = __float2bfloat16(ufe[i]);
        else if (i < 1664000) g_ifeb[i - 640000]  = __float2bfloat16(ife[i - 640000]);
        else                  g_web [i - 1664000] = __float2bfloat16(we [i - 1664000]);
    }
    for (int i = i0; i < WTOT; i += st) {
        const float* src; int loc, dbase, K;
        if      (i < OFF_I)  { src = uW; loc = i - OFF_U;  dbase = OFF_U;  K = 320; }
        else if (i < OFF_W0) { src = iW; loc = i - OFF_I;  dbase = OFF_I;  K = 320; }
        else if (i < OFF_W1) { src = w0; loc = i - OFF_W0; dbase = OFF_W0; K = 256; }
        else if (i < OFF_V0) { src = w1; loc = i - OFF_W1; dbase = OFF_W1; K = 256; }
        else if (i < OFF_V1) { src = v0; loc = i - OFF_V0; dbase = OFF_V0; K = 128; }
        else                 { src = v1; loc = i - OFF_V1; dbase = OFF_V1; K = 128; }
        int k = loc >> 7, n = loc & 127;
        g_wth[dbase + n * K + k] = __float2half(src[loc]);
    }
    for (int i = i0; i < NNODE; i += st) g_deg[i] = 0;
}

// ======== embed (fp16 output) + degree count ========
__global__ void embed_deg_kernel(const int* __restrict__ uf,  const int* __restrict__ itf,
                                 const int* __restrict__ ut,  const int* __restrict__ it,
                                 const int* __restrict__ dstp) {
    if (blockIdx.x >= EMB_BLKS) {
        int i = (blockIdx.x - EMB_BLKS) * blockDim.x + threadIdx.x;
        if (i < EE) atomicAdd(&g_deg[dstp[i]], 1);
        return;
    }
    int gw   = (blockIdx.x * blockDim.x + threadIdx.x) >> 5;
    int lane = threadIdx.x & 31;
    if (gw >= NNODE) return;
    int n = gw;
    bool user = n < NUSR;
    const int* f = user ? uf + (size_t)n * 10 : itf + (size_t)(n - NUSR) * 10;
    const __nv_bfloat16* tab = user ? g_ufeb : g_ifeb;

    float4 a = make_float4(0.f, 0.f, 0.f, 0.f);
#pragma unroll
    for (int j = 0; j < 10; j++) {
        int r = __ldg(f + j);
        uint2 v = __ldg((const uint2*)(tab + (size_t)r * DD) + lane);
        float2 p0 = __bfloat1622float2(*(__nv_bfloat162*)&v.x);
        float2 p1 = __bfloat1622float2(*(__nv_bfloat162*)&v.y);
        a.x += p0.x; a.y += p0.y; a.z += p1.x; a.w += p1.y;
    }
    __half* catrow = g_cat16 + (size_t)n * KCAT;
    __half2 h01 = __floats2half2_rn(a.x * 0.1f, a.y * 0.1f);
    __half2 h23 = __floats2half2_rn(a.z * 0.1f, a.w * 0.1f);
    uint2 pk;
    pk.x = *(uint32_t*)&h01; pk.y = *(uint32_t*)&h23;
    ((uint2*)catrow)[lane] = pk;

    const int* t = user ? ut + (size_t)n * 24 : it + (size_t)(n - NUSR) * 24;
#pragma unroll
    for (int fl = 0; fl < 3; fl++) {
        float2 b = make_float2(0.f, 0.f);
#pragma unroll
        for (int w = 0; w < 8; w++) {
            int r = __ldg(t + fl * 8 + w);
            uint32_t v = __ldg((const uint32_t*)(g_web + (size_t)r * HALFD) + lane);
            float2 p = __bfloat1622float2(*(__nv_bfloat162*)&v);
            b.x += p.x; b.y += p.y;
        }
        __half2 hb = __floats2half2_rn(b.x * 0.125f, b.y * 0.125f);
        *(uint32_t*)(catrow + 128 + fl * 64 + lane * 2) = *(uint32_t*)&hb;
    }
}

// -------- scans --------
__global__ void scan1_kernel() {
    __shared__ int sm[256];
    int tid = threadIdx.x;
    int i = blockIdx.x * 256 + tid;
    int v = (i < NNODE) ? g_deg[i] : 0;
    sm[tid] = v;
    __syncthreads();
#pragma unroll
    for (int d = 1; d < 256; d <<= 1) {
        int t = (tid >= d) ? sm[tid - d] : 0;
        __syncthreads();
        sm[tid] += t;
        __syncthreads();
    }
    if (i < NNODE) g_offs[i] = sm[tid] - v;
    if (tid == 255) g_bsum[blockIdx.x] = sm[255];
}

__global__ void scan2_kernel() {
    __shared__ int sm[1024];
    int tid = threadIdx.x;
    int v = (tid < NBLK) ? g_bsum[tid] : 0;
    sm[tid] = v;
    __syncthreads();
#pragma unroll
    for (int d = 1; d < 1024; d <<= 1) {
        int t = (tid >= d) ? sm[tid - d] : 0;
        __syncthreads();
        sm[tid] += t;
        __syncthreads();
    }
    g_bsum[tid] = sm[tid] - v;
}

__global__ void scan3_kernel() {
    int i = blockIdx.x * blockDim.x + threadIdx.x;
    if (i < NNODE) {
        int o = g_offs[i] + g_bsum[i >> 8];
        g_offs[i] = o;
        g_cursor[i] = o;
    }
    if (i == 0) g_offs[NNODE] = EE;
}

// -------- gather aggregation fp16->fp32->fp16 (warp per node) --------
__global__ void agg_kernel() {
    int gw   = (blockIdx.x * blockDim.x + threadIdx.x) >> 5;
    int lane = threadIdx.x & 31;
    if (gw >= NNODE) return;
    int off = g_offs[gw];
    int end = g_offs[gw + 1];
    float4 acc = make_float4(0.f, 0.f, 0.f, 0.f);
    for (int j = off; j < end; j++) {
        int s = __ldg(&g_csr[j]);
        uint2 v = __ldg((const uint2*)(g_x16 + (size_t)s * DD) + lane);
        float2 p0 = __half22float2(*(__half2*)&v.x);
        float2 p1 = __half22float2(*(__half2*)&v.y);
        acc.x += p0.x; acc.y += p0.y; acc.z += p1.x; acc.w += p1.y;
    }
    float sc = 1.0f / fmaxf((float)(end - off), 1.0f);
    __half2 p0 = __floats2half2_rn(acc.x * sc, acc.y * sc);
    __half2 p1 = __floats2half2_rn(acc.z * sc, acc.w * sc);
    uint2 pk;
    pk.x = *(uint32_t*)&p0; pk.y = *(uint32_t*)&p1;
    ((uint2*)(g_agg16 + (size_t)gw * DD))[lane] = pk;
}

// ======== fp16 projection GEMM (blocks [0,PROJ_BLKS)) + CSR fill (beyond) ========
// x16[row] = cat16[row,320] @ W^T + bias + id_emb ; BK=32 (10 tiles), A dist-2 / W dist-1
// dyn smem (halves): As[3][128][PSTR] | Ws[2][128][PSTR]
__global__ __launch_bounds__(256) void proj_fill(
    const float* __restrict__ ubias, const float* __restrict__ ibias,
    const float* __restrict__ uid,   const float* __restrict__ iid,
    const int* __restrict__ srcp, const int* __restrict__ dstp)
{
    if (blockIdx.x >= PROJ_BLKS) {
        int i = (blockIdx.x - PROJ_BLKS) * blockDim.x + threadIdx.x;
        if (i < EE) {
            int d = dstp[i];
            int pos = atomicAdd(&g_cursor[d], 1);
            g_csr[pos] = srcp[i];
        }
        return;
    }

    extern __shared__ __half smh[];
    __half* As = smh;                       // 3*128*PSTR
    __half* Ws = smh + 3 * 128 * PSTR;      // 2*128*PSTR

    bool user = blockIdx.x < UBLKS;
    const __half* A      = user ? g_cat16 : g_cat16 + (size_t)NUSR * KCAT;
    const __half* Wt     = g_wth + (user ? OFF_U : OFF_I);   // [n][320]
    const float* bias    = user ? ubias : ibias;
    const float* addmat  = user ? uid : iid;
    __half* out          = user ? g_x16 : g_x16 + (size_t)NUSR * DD;
    int M                = user ? NUSR : NITM;
    int r0               = (user ? blockIdx.x : blockIdx.x - UBLKS) * 128;

    int tid  = threadIdx.x;
    int lane = tid & 31;
    int wid  = tid >> 5;
    int wm = wid & 1, wn = wid >> 1;
    int g  = lane >> 2, tg = lane & 3;

    float acc[4][4][4];
#pragma unroll
    for (int mt = 0; mt < 4; mt++)
#pragma unroll
        for (int nt = 0; nt < 4; nt++)
#pragma unroll
            for (int u = 0; u < 4; u++) acc[mt][nt][u] = 0.f;

    const int T = KCAT / 32;   // 10
    auto issueA = [&](int t, int s) {
#pragma unroll
        for (int l = 0; l < 2; l++) {
            int idx = tid + l * 256;
            int m = idx >> 2, c4 = idx & 3;      // 4 chunks of 8 halves per row
            int row = r0 + m;
            cp16(As + (size_t)s * 128 * PSTR + m * PSTR + c4 * 8,
                 A + (size_t)row * KCAT + t * 32 + c4 * 8, row < M);
        }
        cp_commit();
    };
    auto issueW = [&](int t, int s) {
#pragma unroll
        for (int l = 0; l < 2; l++) {
            int idx = tid + l * 256;
            int n = idx >> 2, c4 = idx & 3;
            cp16(Ws + (size_t)s * 128 * PSTR + n * PSTR + c4 * 8,
                 Wt + (size_t)n * KCAT + t * 32 + c4 * 8, true);
        }
        cp_commit();
    };

    issueW(0, 0);
    issueA(0, 0);
    issueA(1, 1);
    for (int t = 0; t < T; t++) {
        int sa = t % 3, sw = t & 1;
        if (t + 1 < T) issueW(t + 1, (t + 1) & 1);
        if (t + 2 < T) issueA(t + 2, (t + 2) % 3);
        if (t + 2 < T) cp_wait3();
        else if (t + 1 < T) cp_wait2();
        else cp_wait0();
        __syncthreads();
        const __half* SA = As + (size_t)sa * 128 * PSTR;
        const __half* SW = Ws + (size_t)sw * 128 * PSTR;
#pragma unroll
        for (int kk = 0; kk < 32; kk += 16) {
            uint32_t afr[4][4];
#pragma unroll
            for (int mt = 0; mt < 4; mt++) {
                int rb = wm * 64 + mt * 16 + g;
                afr[mt][0] = *(const uint32_t*)(SA + rb * PSTR + kk + 2 * tg);
                afr[mt][1] = *(const uint32_t*)(SA + (rb + 8) * PSTR + kk + 2 * tg);
                afr[mt][2] = *(const uint32_t*)(SA + rb * PSTR + kk + 2 * tg + 8);
                afr[mt][3] = *(const uint32_t*)(SA + (rb + 8) * PSTR + kk + 2 * tg + 8);
            }
            uint32_t bfr[4][2];
#pragma unroll
            for (int nt = 0; nt < 4; nt++) {
                int nn = wn * 32 + nt * 8 + g;
                bfr[nt][0] = *(const uint32_t*)(SW + nn * PSTR + kk + 2 * tg);
                bfr[nt][1] = *(const uint32_t*)(SW + nn * PSTR + kk + 2 * tg + 8);
            }
#pragma unroll
            for (int mt = 0; mt < 4; mt++)
#pragma unroll
                for (int nt = 0; nt < 4; nt++)
                    mma_f16(acc[mt][nt], afr[mt], bfr[nt]);
        }
        __syncthreads();
    }

#pragma unroll
    for (int mt = 0; mt < 4; mt++) {
#pragma unroll
        for (int nt = 0; nt < 4; nt++) {
            int col = wn * 32 + nt * 8 + tg * 2;
            int rowa = r0 + wm * 64 + mt * 16 + g;
            int rowb = rowa + 8;
            float b0 = bias[col], b1 = bias[col + 1];
            if (rowa < M) {
                float x0 = acc[mt][nt][0] + b0 + addmat[(size_t)rowa * 128 + col];
                float x1 = acc[mt][nt][1] + b1 + addmat[(size_t)rowa * 128 + col + 1];
                *(__half2*)(out + (size_t)rowa * 128 + col) = __floats2half2_rn(x0, x1);
            }
            if (rowb < M) {
                float x2 = acc[mt][nt][2] + b0 + addmat[(size_t)rowb * 128 + col];
                float x3 = acc[mt][nt][3] + b1 + addmat[(size_t)rowb * 128 + col + 1];
                *(__half2*)(out + (size_t)rowb * 128 + col) = __floats2half2_rn(x2, x3);
            }
        }
    }
}

// ======== fused SAGE layer fp16: 24 tiles BK=16 ========
// t 0..7: agg16 @ vW^T -> h (fp16, smem Hs); t 8..15: x16 @ wW^T[0:128];
// t 16..23: Hs @ wW^T[128:256]
// dyn smem (halves): As[3][128][SSTR] | Ws[2][128][SSTR] | Hs[128][128] (word-XOR swizzle)
template <bool RELU, bool OUT16>
__global__ __launch_bounds__(256) void sage_layer(
    int voff, const float* __restrict__ vb,
    int woff, const float* __restrict__ wb,
    float* __restrict__ outf, int M)
{
    extern __shared__ __half smh[];
    __half*  As = smh;                           // 3*128*SSTR
    __half*  Ws = smh + 3 * 128 * SSTR;          // 2*128*SSTR
    __half2* H2 = (__half2*)(smh + 3 * 128 * SSTR + 2 * 128 * SSTR);  // 128*64 words
    const __half* vW = g_wth + voff;   // [n][128]
    const __half* wW = g_wth + woff;   // [n][256]

    int tid  = threadIdx.x;
    int lane = tid & 31;
    int wid  = tid >> 5;
    int wm = wid & 1, wn = wid >> 1;
    int g  = lane >> 2, tg = lane & 3;
    int r0 = blockIdx.x * 128;

    float acc[4][4][4];
#pragma unroll
    for (int mt = 0; mt < 4; mt++)
#pragma unroll
        for (int nt = 0; nt < 4; nt++)
#pragma unroll
            for (int u = 0; u < 4; u++) acc[mt][nt][u] = 0.f;

    auto issueA = [&](int at, int s) {
        const __half* Ap = (at < 8) ? g_agg16 : g_x16;
        int kt = (at < 8) ? at : at - 8;
        int idx = tid;                      // 256 chunks: row*2 + c2
        int m = idx >> 1, c2 = idx & 1;
        int row = r0 + m;
        cp16(As + (size_t)s * 128 * SSTR + m * SSTR + c2 * 8,
             Ap + (size_t)row * DD + kt * 16 + c2 * 8, row < M);
        cp_commit();
    };
    auto issueW = [&](int wt, int s) {
        int idx = tid;
        int n = idx >> 1, c2 = idx & 1;
        const __half* src = (wt < 8) ? (vW + (size_t)n * 128 + wt * 16)
                                     : (wW + (size_t)n * 256 + (wt - 8) * 16);
        cp16(Ws + (size_t)s * 128 * SSTR + n * SSTR + c2 * 8, src + c2 * 8, true);
        cp_commit();
    };

    issueW(0, 0);
    issueA(0, 0);
    issueA(1, 1);

    for (int t = 0; t < 24; t++) {
        int sa = t % 3, sw = t & 1;
        if (t + 1 < 24) issueW(t + 1, (t + 1) & 1);
        if (t + 2 < 16) issueA(t + 2, (t + 2) % 3);
        if (t < 14) cp_wait3();
        else if (t == 14) cp_wait2();
        else if (t < 23) cp_wait1();
        else cp_wait0();
        __syncthreads();

        const __half* SA = As + (size_t)sa * 128 * SSTR;
        const __half* SW = Ws + (size_t)sw * 128 * SSTR;
        int hcp = (t - 16) * 8;   // half-pair base for Hs reads
        {
            uint32_t afr[4][4];
#pragma unroll
            for (int mt = 0; mt < 4; mt++) {
                int rb = wm * 64 + mt * 16 + g;
                if (t < 16) {
                    afr[mt][0] = *(const uint32_t*)(SA + rb * SSTR + 2 * tg);
                    afr[mt][1] = *(const uint32_t*)(SA + (rb + 8) * SSTR + 2 * tg);
                    afr[mt][2] = *(const uint32_t*)(SA + rb * SSTR + 2 * tg + 8);
                    afr[mt][3] = *(const uint32_t*)(SA + (rb + 8) * SSTR + 2 * tg + 8);
                } else {
                    int xr = (rb & 7) << 2;
                    afr[mt][0] = *(const uint32_t*)&H2[rb * 64 + ((hcp + tg) ^ xr)];
                    afr[mt][1] = *(const uint32_t*)&H2[(rb + 8) * 64 + ((hcp + tg) ^ xr)];
                    afr[mt][2] = *(const uint32_t*)&H2[rb * 64 + ((hcp + tg + 4) ^ xr)];
                    afr[mt][3] = *(const uint32_t*)&H2[(rb + 8) * 64 + ((hcp + tg + 4) ^ xr)];
                }
            }
            uint32_t bfr[4][2];
#pragma unroll
            for (int nt = 0; nt < 4; nt++) {
                int nn = wn * 32 + nt * 8 + g;
                bfr[nt][0] = *(const uint32_t*)(SW + nn * SSTR + 2 * tg);
                bfr[nt][1] = *(const uint32_t*)(SW + nn * SSTR + 2 * tg + 8);
            }
#pragma unroll
            for (int mt = 0; mt < 4; mt++)
#pragma unroll
                for (int nt = 0; nt < 4; nt++)
                    mma_f16(acc[mt][nt], afr[mt], bfr[nt]);
        }

        if (t == 7) {
            // h = relu(acc + vb) -> Hs (fp16, swizzled), reset acc
#pragma unroll
            for (int mt = 0; mt < 4; mt++) {
#pragma unroll
                for (int nt = 0; nt < 4; nt++) {
                    int col = wn * 32 + nt * 8 + tg * 2;
                    int ra = wm * 64 + mt * 16 + g;
                    int cp = col >> 1;
                    int xr = (ra & 7) << 2;
                    float b0 = vb[col], b1 = vb[col + 1];
                    H2[ra * 64 + (cp ^ xr)] =
                        __floats2half2_rn(fmaxf(acc[mt][nt][0] + b0, 0.f),
                                          fmaxf(acc[mt][nt][1] + b1, 0.f));
                    H2[(ra + 8) * 64 + (cp ^ xr)] =
                        __floats2half2_rn(fmaxf(acc[mt][nt][2] + b0, 0.f),
                                          fmaxf(acc[mt][nt][3] + b1, 0.f));
#pragma unroll
                    for (int u = 0; u < 4; u++) acc[mt][nt][u] = 0.f;
                }
            }
        }
        __syncthreads();
    }

    // epilogue
#pragma unroll
    for (int mt = 0; mt < 4; mt++) {
#pragma unroll
        for (int nt = 0; nt < 4; nt++) {
            int col = wn * 32 + nt * 8 + tg * 2;
            int rowa = r0 + wm * 64 + mt * 16 + g;
            int rowb = rowa + 8;
            float b0 = wb[col], b1 = wb[col + 1];
            float x0 = acc[mt][nt][0] + b0, x1 = acc[mt][nt][1] + b1;
            float x2 = acc[mt][nt][2] + b0, x3 = acc[mt][nt][3] + b1;
            if (RELU) {
                x0 = fmaxf(x0, 0.f); x1 = fmaxf(x1, 0.f);
                x2 = fmaxf(x2, 0.f); x3 = fmaxf(x3, 0.f);
            }
            if (OUT16) {
                if (rowa < M)
                    *(__half2*)(g_x16 + (size_t)rowa * 128 + col) = __floats2half2_rn(x0, x1);
                if (rowb < M)
                    *(__half2*)(g_x16 + (size_t)rowb * 128 + col) = __floats2half2_rn(x2, x3);
            } else {
                if (rowa < M)
                    *(float2*)(outf + (size_t)rowa * 128 + col) = make_float2(x0, x1);
                if (rowb < M)
                    *(float2*)(outf + (size_t)rowb * 128 + col) = make_float2(x2, x3);
            }
        }
    }
}

// -------- launch --------
extern "C" void kernel_launch(void* const* d_in, const int* in_sizes, int n_in,
                              void* d_out, int out_size) {
    const int*   edge          = (const int*)d_in[0];
    const int*   src           = edge;
    const int*   dstp          = edge + EE;
    const int*   user_features = (const int*)d_in[1];
    const int*   item_features = (const int*)d_in[2];
    const int*   user_text     = (const int*)d_in[3];
    const int*   item_text     = (const int*)d_in[4];
    const float* user_id_emb   = (const float*)d_in[5];
    const float* item_id_emb   = (const float*)d_in[6];
    const float* user_feat_emb = (const float*)d_in[7];
    const float* item_feat_emb = (const float*)d_in[8];
    const float* word_emb      = (const float*)d_in[9];
    const float* user_projW    = (const float*)d_in[10];
    const float* user_projb    = (const float*)d_in[11];
    const float* item_projW    = (const float*)d_in[12];
    const float* item_projb    = (const float*)d_in[13];
    const float* w0W = (const float*)d_in[14];
    const float* w0b = (const float*)d_in[15];
    const float* w1W = (const float*)d_in[16];
    const float* w1b = (const float*)d_in[17];
    const float* v0W = (const float*)d_in[18];
    const float* v0b = (const float*)d_in[19];
    const float* v1W = (const float*)d_in[20];
    const float* v1b = (const float*)d_in[21];

    const int PROJ_SMEM = (3 * 128 * PSTR + 2 * 128 * PSTR) * 2;                 // 51200
    const int SAGE_SMEM = (3 * 128 * SSTR + 2 * 128 * SSTR) * 2 + 128 * 128 * 2; // 63488
    cudaFuncSetAttribute(proj_fill, cudaFuncAttributeMaxDynamicSharedMemorySize, PROJ_SMEM);
    cudaFuncSetAttribute(sage_layer<true, true>,   cudaFuncAttributeMaxDynamicSharedMemorySize, SAGE_SMEM);
    cudaFuncSetAttribute(sage_layer<false, false>, cudaFuncAttributeMaxDynamicSharedMemorySize, SAGE_SMEM);

    // 0: tables->bf16, weights->fp16^T, zero deg
    prep_kernel<<<2048, 256>>>(user_feat_emb, item_feat_emb, word_emb,
                               user_projW, item_projW, w0W, w1W, v0W, v1W);
    // 1: embed fp16 (+ deg counting riding along)
    embed_deg_kernel<<<EMB_BLKS + EDGE_BLKS, 256>>>(
        user_features, item_features, user_text, item_text, dstp);
    // 2-4: exclusive scan of degrees
    scan1_kernel<<<NBLK, 256>>>();
    scan2_kernel<<<1, 1024>>>();
    scan3_kernel<<<(NNODE + 255) / 256, 256>>>();
    // 5: fp16 projection GEMM (+ CSR fill riding along) -> g_x16
    proj_fill<<<PROJ_BLKS + EDGE_BLKS, 256, PROJ_SMEM>>>(
        user_projb, item_projb, user_id_emb, item_id_emb, src, dstp);

    // ----- layer 0 -----
    agg_kernel<<<(NNODE * 32 + 255) / 256, 256>>>();
    sage_layer<true, true><<<(NNODE + 127) / 128, 256, SAGE_SMEM>>>(
        OFF_V0, v0b, OFF_W0, w0b, nullptr, NNODE);

    // ----- layer 1 -----
    agg_kernel<<<(NNODE * 32 + 255) / 256, 256>>>();
    sage_layer<false, false><<<(NNODE + 127) / 128, 256, SAGE_SMEM>>>(
        OFF_V1, v1b, OFF_W1, w1b, (float*)d_out, NNODE);
}

// round 15
// speedup vs baseline: 1.6046x; 1.1466x over previous
#include <cuda_runtime.h>
#include <cuda_bf16.h>
#include <cuda_fp16.h>
#include <cstdint>

#define NUSR 100000
#define NITM 50000
#define NNODE (NUSR + NITM)
#define DD 128
#define EE 1500000
#define HALFD 64
#define KCAT 320
#define NBLK 586     // ceil(NNODE/256)
#define UBLKS 782    // ceil(NUSR/128)
#define IBLKS 391    // ceil(NITM/128)
#define PROJ_BLKS (UBLKS + IBLKS)
#define EMB_BLKS 18750   // ceil(NNODE*32/256)
#define EDGE_BLKS 5860   // ceil(EE/256)

// fp16 weight buffer offsets (halves), transposed [n][K] per matrix
#define OFF_U  0
#define OFF_I  40960
#define OFF_W0 81920
#define OFF_W1 114688
#define OFF_V0 147456
#define OFF_V1 163840
#define WTOT   180224

// smem strides (halves) — conflict-free for ldmatrix phases
#define PSTR 40   // proj tiles: 32 data + 8 pad
#define SSTR 24   // sage tiles: 16 data + 8 pad

// -------- scratch (device globals: allocation-free) --------
__device__ __half g_cat16[(size_t)NNODE * KCAT];
__device__ __half g_x16  [(size_t)NNODE * DD];
__device__ __half g_agg16[(size_t)NNODE * DD];
__device__ __half g_wth  [WTOT];
__device__ int    g_deg[NNODE];
__device__ int    g_bsum[1024];
__device__ int    g_offs[NNODE + 1];
__device__ int    g_cursor[NNODE];
__device__ int    g_csr[EE];
__device__ __nv_bfloat16 g_ufeb[5000 * 128];
__device__ __nv_bfloat16 g_ifeb[8000 * 128];
__device__ __nv_bfloat16 g_web [30000 * 64];

// -------- fp16 mma helper: m16n8k16, fp32 accumulate --------
__device__ __forceinline__ void mma_f16(float* c, const uint32_t* a, const uint32_t* b) {
    asm volatile(
        "mma.sync.aligned.m16n8k16.row.col.f32.f16.f16.f32 "
        "{%0,%1,%2,%3}, {%4,%5,%6,%7}, {%8,%9}, {%0,%1,%2,%3};"
        : "+f"(c[0]), "+f"(c[1]), "+f"(c[2]), "+f"(c[3])
        : "r"(a[0]), "r"(a[1]), "r"(a[2]), "r"(a[3]), "r"(b[0]), "r"(b[1]));
}

__device__ __forceinline__ void ldsm4(uint32_t* r, uint32_t addr) {
    asm volatile("ldmatrix.sync.aligned.m8n8.x4.shared.b16 {%0,%1,%2,%3}, [%4];"
                 : "=r"(r[0]), "=r"(r[1]), "=r"(r[2]), "=r"(r[3]) : "r"(addr));
}

__device__ __forceinline__ void cp16(void* smem_dst, const void* gsrc, bool pred) {
    uint32_t dst = (uint32_t)__cvta_generic_to_shared(smem_dst);
    int sz = pred ? 16 : 0;
    asm volatile("cp.async.ca.shared.global [%0], [%1], 16, %2;\n"
                 :: "r"(dst), "l"(gsrc), "r"(sz));
}
__device__ __forceinline__ void cp_commit() { asm volatile("cp.async.commit_group;\n"); }
__device__ __forceinline__ void cp_wait0()  { asm volatile("cp.async.wait_group 0;\n"); }
__device__ __forceinline__ void cp_wait1()  { asm volatile("cp.async.wait_group 1;\n"); }
__device__ __forceinline__ void cp_wait2()  { asm volatile("cp.async.wait_group 2;\n"); }
__device__ __forceinline__ void cp_wait3()  { asm volatile("cp.async.wait_group 3;\n"); }

// ======== prep: tables->bf16, weights->fp16 transposed [n][K], zero deg ========
__global__ void prep_kernel(const float* __restrict__ ufe, const float* __restrict__ ife,
                            const float* __restrict__ we,
                            const float* __restrict__ uW, const float* __restrict__ iW,
                            const float* __restrict__ w0, const float* __restrict__ w1,
                            const float* __restrict__ v0, const float* __restrict__ v1) {
    int i0 = blockIdx.x * blockDim.x + threadIdx.x;
    int st = gridDim.x * blockDim.x;
    for (int i = i0; i < 3584000; i += st) {
        if      (i < 640000)  g_ufeb[i]           = __float2bfloat16(ufe[i]);
        else if (i < 1664000) g_ifeb[i - 640000]  = __float2bfloat16(ife[i - 640000]);
        else                  g_web [i - 1664000] = __float2bfloat16(we [i - 1664000]);
    }
    for (int i = i0; i < WTOT; i += st) {
        const float* src; int loc, dbase, K;
        if      (i < OFF_I)  { src = uW; loc = i - OFF_U;  dbase = OFF_U;  K = 320; }
        else if (i < OFF_W0) { src = iW; loc = i - OFF_I;  dbase = OFF_I;  K = 320; }
        else if (i < OFF_W1) { src = w0; loc = i - OFF_W0; dbase = OFF_W0; K = 256; }
        else if (i < OFF_V0) { src = w1; loc = i - OFF_W1; dbase = OFF_W1; K = 256; }
        else if (i < OFF_V1) { src = v0; loc = i - OFF_V0; dbase = OFF_V0; K = 128; }
        else                 { src = v1; loc = i - OFF_V1; dbase = OFF_V1; K = 128; }
        int k = loc >> 7, n = loc & 127;
        g_wth[dbase + n * K + k] = __float2half(src[loc]);
    }
    for (int i = i0; i < NNODE; i += st) g_deg[i] = 0;
}

// ======== embed (fp16 output) + degree count ========
__global__ void embed_deg_kernel(const int* __restrict__ uf,  const int* __restrict__ itf,
                                 const int* __restrict__ ut,  const int* __restrict__ it,
                                 const int* __restrict__ dstp) {
    if (blockIdx.x >= EMB_BLKS) {
        int i = (blockIdx.x - EMB_BLKS) * blockDim.x + threadIdx.x;
        if (i < EE) atomicAdd(&g_deg[dstp[i]], 1);
        return;
    }
    int gw   = (blockIdx.x * blockDim.x + threadIdx.x) >> 5;
    int lane = threadIdx.x & 31;
    if (gw >= NNODE) return;
    int n = gw;
    bool user = n < NUSR;
    const int* f = user ? uf + (size_t)n * 10 : itf + (size_t)(n - NUSR) * 10;
    const __nv_bfloat16* tab = user ? g_ufeb : g_ifeb;

    float4 a = make_float4(0.f, 0.f, 0.f, 0.f);
#pragma unroll
    for (int j = 0; j < 10; j++) {
        int r = __ldg(f + j);
        uint2 v = __ldg((const uint2*)(tab + (size_t)r * DD) + lane);
        float2 p0 = __bfloat1622float2(*(__nv_bfloat162*)&v.x);
        float2 p1 = __bfloat1622float2(*(__nv_bfloat162*)&v.y);
        a.x += p0.x; a.y += p0.y; a.z += p1.x; a.w += p1.y;
    }
    __half* catrow = g_cat16 + (size_t)n * KCAT;
    __half2 h01 = __floats2half2_rn(a.x * 0.1f, a.y * 0.1f);
    __half2 h23 = __floats2half2_rn(a.z * 0.1f, a.w * 0.1f);
    uint2 pk;
    pk.x = *(uint32_t*)&h01; pk.y = *(uint32_t*)&h23;
    ((uint2*)catrow)[lane] = pk;

    const int* t = user ? ut + (size_t)n * 24 : it + (size_t)(n - NUSR) * 24;
#pragma unroll
    for (int fl = 0; fl < 3; fl++) {
        float2 b = make_float2(0.f, 0.f);
#pragma unroll
        for (int w = 0; w < 8; w++) {
            int r = __ldg(t + fl * 8 + w);
            uint32_t v = __ldg((const uint32_t*)(g_web + (size_t)r * HALFD) + lane);
            float2 p = __bfloat1622float2(*(__nv_bfloat162*)&v);
            b.x += p.x; b.y += p.y;
        }
        __half2 hb = __floats2half2_rn(b.x * 0.125f, b.y * 0.125f);
        *(uint32_t*)(catrow + 128 + fl * 64 + lane * 2) = *(uint32_t*)&hb;
    }
}

// -------- scans --------
__global__ void scan1_kernel() {
    __shared__ int sm[256];
    int tid = threadIdx.x;
    int i = blockIdx.x * 256 + tid;
    int v = (i < NNODE) ? g_deg[i] : 0;
    sm[tid] = v;
    __syncthreads();
#pragma unroll
    for (int d = 1; d < 256; d <<= 1) {
        int t = (tid >= d) ? sm[tid - d] : 0;
        __syncthreads();
        sm[tid] += t;
        __syncthreads();
    }
    if (i < NNODE) g_offs[i] = sm[tid] - v;
    if (tid == 255) g_bsum[blockIdx.x] = sm[255];
}

__global__ void scan2_kernel() {
    __shared__ int sm[1024];
    int tid = threadIdx.x;
    int v = (tid < NBLK) ? g_bsum[tid] : 0;
    sm[tid] = v;
    __syncthreads();
#pragma unroll
    for (int d = 1; d < 1024; d <<= 1) {
        int t = (tid >= d) ? sm[tid - d] : 0;
        __syncthreads();
        sm[tid] += t;
        __syncthreads();
    }
    g_bsum[tid] = sm[tid] - v;
}

__global__ void scan3_kernel() {
    int i = blockIdx.x * blockDim.x + threadIdx.x;
    if (i < NNODE) {
        int o = g_offs[i] + g_bsum[i >> 8];
        g_offs[i] = o;
        g_cursor[i] = o;
    }
    if (i == 0) g_offs[NNODE] = EE;
}

// -------- gather aggregation fp16, 4-way unrolled (warp per node) --------
__global__ void agg_kernel() {
    int gw   = (blockIdx.x * blockDim.x + threadIdx.x) >> 5;
    int lane = threadIdx.x & 31;
    if (gw >= NNODE) return;
    int off = g_offs[gw];
    int end = g_offs[gw + 1];
    float4 acc = make_float4(0.f, 0.f, 0.f, 0.f);
    int j = off;
    for (; j + 4 <= end; j += 4) {
        int s0 = __ldg(&g_csr[j]);
        int s1 = __ldg(&g_csr[j + 1]);
        int s2 = __ldg(&g_csr[j + 2]);
        int s3 = __ldg(&g_csr[j + 3]);
        uint2 v0 = __ldg((const uint2*)(g_x16 + (size_t)s0 * DD) + lane);
        uint2 v1 = __ldg((const uint2*)(g_x16 + (size_t)s1 * DD) + lane);
        uint2 v2 = __ldg((const uint2*)(g_x16 + (size_t)s2 * DD) + lane);
        uint2 v3 = __ldg((const uint2*)(g_x16 + (size_t)s3 * DD) + lane);
#pragma unroll
        for (int q = 0; q < 4; q++) {
            uint2 v = (q == 0) ? v0 : (q == 1) ? v1 : (q == 2) ? v2 : v3;
            float2 p0 = __half22float2(*(__half2*)&v.x);
            float2 p1 = __half22float2(*(__half2*)&v.y);
            acc.x += p0.x; acc.y += p0.y; acc.z += p1.x; acc.w += p1.y;
        }
    }
    for (; j < end; j++) {
        int s = __ldg(&g_csr[j]);
        uint2 v = __ldg((const uint2*)(g_x16 + (size_t)s * DD) + lane);
        float2 p0 = __half22float2(*(__half2*)&v.x);
        float2 p1 = __half22float2(*(__half2*)&v.y);
        acc.x += p0.x; acc.y += p0.y; acc.z += p1.x; acc.w += p1.y;
    }
    float sc = 1.0f / fmaxf((float)(end - off), 1.0f);
    __half2 p0 = __floats2half2_rn(acc.x * sc, acc.y * sc);
    __half2 p1 = __floats2half2_rn(acc.z * sc, acc.w * sc);
    uint2 pk;
    pk.x = *(uint32_t*)&p0; pk.y = *(uint32_t*)&p1;
    ((uint2*)(g_agg16 + (size_t)gw * DD))[lane] = pk;
}

// ======== fp16 projection GEMM (blocks [0,PROJ_BLKS)) + CSR fill (beyond) ========
__global__ __launch_bounds__(256) void proj_fill(
    const float* __restrict__ ubias, const float* __restrict__ ibias,
    const float* __restrict__ uid,   const float* __restrict__ iid,
    const int* __restrict__ srcp, const int* __restrict__ dstp)
{
    if (blockIdx.x >= PROJ_BLKS) {
        int i = (blockIdx.x - PROJ_BLKS) * blockDim.x + threadIdx.x;
        if (i < EE) {
            int d = dstp[i];
            int pos = atomicAdd(&g_cursor[d], 1);
            g_csr[pos] = srcp[i];
        }
        return;
    }

    extern __shared__ __half smh[];
    __half* As = smh;                       // 3*128*PSTR
    __half* Ws = smh + 3 * 128 * PSTR;      // 2*128*PSTR

    bool user = blockIdx.x < UBLKS;
    const __half* A      = user ? g_cat16 : g_cat16 + (size_t)NUSR * KCAT;
    const __half* Wt     = g_wth + (user ? OFF_U : OFF_I);
    const float* bias    = user ? ubias : ibias;
    const float* addmat  = user ? uid : iid;
    __half* out          = user ? g_x16 : g_x16 + (size_t)NUSR * DD;
    int M                = user ? NUSR : NITM;
    int r0               = (user ? blockIdx.x : blockIdx.x - UBLKS) * 128;

    int tid  = threadIdx.x;
    int lane = tid & 31;
    int wid  = tid >> 5;
    int wm = wid & 1, wn = wid >> 1;
    int g  = lane >> 2, tg = lane & 3;
    // ldmatrix lane decomposition
    int lrow = (lane & 7) + ((lane & 8) ? 8 : 0);   // A: row offset within 16
    int lka  = (lane & 16) ? 8 : 0;                 // A: k offset
    int lnc  = (lane & 7) + ((lane & 16) ? 8 : 0);  // B: n offset within 16
    int lkb  = (lane & 8) ? 8 : 0;                  // B: k offset

    uint32_t as_sm = (uint32_t)__cvta_generic_to_shared(As);
    uint32_t ws_sm = (uint32_t)__cvta_generic_to_shared(Ws);

    float acc[4][4][4];
#pragma unroll
    for (int mt = 0; mt < 4; mt++)
#pragma unroll
        for (int nt = 0; nt < 4; nt++)
#pragma unroll
            for (int u = 0; u < 4; u++) acc[mt][nt][u] = 0.f;

    const int T = KCAT / 32;
    auto issueA = [&](int t, int s) {
#pragma unroll
        for (int l = 0; l < 2; l++) {
            int idx = tid + l * 256;
            int m = idx >> 2, c4 = idx & 3;
            int row = r0 + m;
            cp16(As + (size_t)s * 128 * PSTR + m * PSTR + c4 * 8,
                 A + (size_t)row * KCAT + t * 32 + c4 * 8, row < M);
        }
        cp_commit();
    };
    auto issueW = [&](int t, int s) {
#pragma unroll
        for (int l = 0; l < 2; l++) {
            int idx = tid + l * 256;
            int n = idx >> 2, c4 = idx & 3;
            cp16(Ws + (size_t)s * 128 * PSTR + n * PSTR + c4 * 8,
                 Wt + (size_t)n * KCAT + t * 32 + c4 * 8, true);
        }
        cp_commit();
    };

    issueW(0, 0);
    issueA(0, 0);
    issueA(1, 1);
    for (int t = 0; t < T; t++) {
        int sa = t % 3, sw = t & 1;
        if (t + 1 < T) issueW(t + 1, (t + 1) & 1);
        if (t + 2 < T) issueA(t + 2, (t + 2) % 3);
        if (t + 2 < T) cp_wait3();
        else if (t + 1 < T) cp_wait2();
        else cp_wait0();
        __syncthreads();
        uint32_t sab = as_sm + (uint32_t)sa * 128 * PSTR * 2;
        uint32_t swb = ws_sm + (uint32_t)sw * 128 * PSTR * 2;
#pragma unroll
        for (int kk = 0; kk < 32; kk += 16) {
            uint32_t afr[4][4];
#pragma unroll
            for (int mt = 0; mt < 4; mt++) {
                int rb0 = wm * 64 + mt * 16;
                ldsm4(afr[mt], sab + ((rb0 + lrow) * PSTR + kk + lka) * 2);
            }
            uint32_t bfr[4][2];
#pragma unroll
            for (int np = 0; np < 2; np++) {
                uint32_t r4[4];
                int nb0 = wn * 32 + np * 16;
                ldsm4(r4, swb + ((nb0 + lnc) * PSTR + kk + lkb) * 2);
                bfr[np * 2][0] = r4[0]; bfr[np * 2][1] = r4[1];
                bfr[np * 2 + 1][0] = r4[2]; bfr[np * 2 + 1][1] = r4[3];
            }
#pragma unroll
            for (int mt = 0; mt < 4; mt++)
#pragma unroll
                for (int nt = 0; nt < 4; nt++)
                    mma_f16(acc[mt][nt], afr[mt], bfr[nt]);
        }
        __syncthreads();
    }

#pragma unroll
    for (int mt = 0; mt < 4; mt++) {
#pragma unroll
        for (int nt = 0; nt < 4; nt++) {
            int col = wn * 32 + nt * 8 + tg * 2;
            int rowa = r0 + wm * 64 + mt * 16 + g;
            int rowb = rowa + 8;
            float b0 = bias[col], b1 = bias[col + 1];
            if (rowa < M) {
                float x0 = acc[mt][nt][0] + b0 + addmat[(size_t)rowa * 128 + col];
                float x1 = acc[mt][nt][1] + b1 + addmat[(size_t)rowa * 128 + col + 1];
                *(__half2*)(out + (size_t)rowa * 128 + col) = __floats2half2_rn(x0, x1);
            }
            if (rowb < M) {
                float x2 = acc[mt][nt][2] + b0 + addmat[(size_t)rowb * 128 + col];
                float x3 = acc[mt][nt][3] + b1 + addmat[(size_t)rowb * 128 + col + 1];
                *(__half2*)(out + (size_t)rowb * 128 + col) = __floats2half2_rn(x2, x3);
            }
        }
    }
}

// ======== fused SAGE layer fp16: 24 tiles BK=16, ldmatrix fragments ========
template <bool RELU, bool OUT16>
__global__ __launch_bounds__(256) void sage_layer(
    int voff, const float* __restrict__ vb,
    int woff, const float* __restrict__ wb,
    float* __restrict__ outf, int M)
{
    extern __shared__ __half smh[];
    __half*  As = smh;                           // 3*128*SSTR
    __half*  Ws = smh + 3 * 128 * SSTR;          // 2*128*SSTR
    __half2* H2 = (__half2*)(smh + 3 * 128 * SSTR + 2 * 128 * SSTR);
    const __half* vW = g_wth + voff;
    const __half* wW = g_wth + woff;

    int tid  = threadIdx.x;
    int lane = tid & 31;
    int wid  = tid >> 5;
    int wm = wid & 1, wn = wid >> 1;
    int g  = lane >> 2, tg = lane & 3;
    int lrow = (lane & 7) + ((lane & 8) ? 8 : 0);
    int lka  = (lane & 16) ? 8 : 0;
    int lnc  = (lane & 7) + ((lane & 16) ? 8 : 0);
    int lkb  = (lane & 8) ? 8 : 0;
    int r0 = blockIdx.x * 128;

    uint32_t as_sm = (uint32_t)__cvta_generic_to_shared(As);
    uint32_t ws_sm = (uint32_t)__cvta_generic_to_shared(Ws);
    uint32_t h2_sm = (uint32_t)__cvta_generic_to_shared(H2);

    float acc[4][4][4];
#pragma unroll
    for (int mt = 0; mt < 4; mt++)
#pragma unroll
        for (int nt = 0; nt < 4; nt++)
#pragma unroll
            for (int u = 0; u < 4; u++) acc[mt][nt][u] = 0.f;

    auto issueA = [&](int at, int s) {
        const __half* Ap = (at < 8) ? g_agg16 : g_x16;
        int kt = (at < 8) ? at : at - 8;
        int m = tid >> 1, c2 = tid & 1;
        int row = r0 + m;
        cp16(As + (size_t)s * 128 * SSTR + m * SSTR + c2 * 8,
             Ap + (size_t)row * DD + kt * 16 + c2 * 8, row < M);
        cp_commit();
    };
    auto issueW = [&](int wt, int s) {
        int n = tid >> 1, c2 = tid & 1;
        const __half* src = (wt < 8) ? (vW + (size_t)n * 128 + wt * 16)
                                     : (wW + (size_t)n * 256 + (wt - 8) * 16);
        cp16(Ws + (size_t)s * 128 * SSTR + n * SSTR + c2 * 8, src + c2 * 8, true);
        cp_commit();
    };

    issueW(0, 0);
    issueA(0, 0);
    issueA(1, 1);

    for (int t = 0; t < 24; t++) {
        int sa = t % 3, sw = t & 1;
        if (t + 1 < 24) issueW(t + 1, (t + 1) & 1);
        if (t + 2 < 16) issueA(t + 2, (t + 2) % 3);
        if (t < 14) cp_wait3();
        else if (t == 14) cp_wait2();
        else if (t < 23) cp_wait1();
        else cp_wait0();
        __syncthreads();

        uint32_t sab = as_sm + (uint32_t)sa * 128 * SSTR * 2;
        uint32_t swb = ws_sm + (uint32_t)sw * 128 * SSTR * 2;
        int hcp = (t - 16) * 8;
        {
            uint32_t afr[4][4];
#pragma unroll
            for (int mt = 0; mt < 4; mt++) {
                int rb0 = wm * 64 + mt * 16;
                if (t < 16) {
                    ldsm4(afr[mt], sab + ((rb0 + lrow) * SSTR + lka) * 2);
                } else {
                    int row = rb0 + lrow;
                    int xr = (row & 7) << 2;
                    int word = (hcp + (lka >> 1)) ^ xr;
                    ldsm4(afr[mt], h2_sm + (row * 64 + word) * 4);
                }
            }
            uint32_t bfr[4][2];
#pragma unroll
            for (int np = 0; np < 2; np++) {
                uint32_t r4[4];
                int nb0 = wn * 32 + np * 16;
                ldsm4(r4, swb + ((nb0 + lnc) * SSTR + lkb) * 2);
                bfr[np * 2][0] = r4[0]; bfr[np * 2][1] = r4[1];
                bfr[np * 2 + 1][0] = r4[2]; bfr[np * 2 + 1][1] = r4[3];
            }
#pragma unroll
            for (int mt = 0; mt < 4; mt++)
#pragma unroll
                for (int nt = 0; nt < 4; nt++)
                    mma_f16(acc[mt][nt], afr[mt], bfr[nt]);
        }

        if (t == 7) {
#pragma unroll
            for (int mt = 0; mt < 4; mt++) {
#pragma unroll
                for (int nt = 0; nt < 4; nt++) {
                    int col = wn * 32 + nt * 8 + tg * 2;
                    int ra = wm * 64 + mt * 16 + g;
                    int cp = col >> 1;
                    float b0 = vb[col], b1 = vb[col + 1];
                    int xra = (ra & 7) << 2;
                    H2[ra * 64 + (cp ^ xra)] =
                        __floats2half2_rn(fmaxf(acc[mt][nt][0] + b0, 0.f),
                                          fmaxf(acc[mt][nt][1] + b1, 0.f));
                    int xrb = ((ra + 8) & 7) << 2;
                    H2[(ra + 8) * 64 + (cp ^ xrb)] =
                        __floats2half2_rn(fmaxf(acc[mt][nt][2] + b0, 0.f),
                                          fmaxf(acc[mt][nt][3] + b1, 0.f));
#pragma unroll
                    for (int u = 0; u < 4; u++) acc[mt][nt][u] = 0.f;
                }
            }
        }
        __syncthreads();
    }

    // epilogue
#pragma unroll
    for (int mt = 0; mt < 4; mt++) {
#pragma unroll
        for (int nt = 0; nt < 4; nt++) {
            int col = wn * 32 + nt * 8 + tg * 2;
            int rowa = r0 + wm * 64 + mt * 16 + g;
            int rowb = rowa + 8;
            float b0 = wb[col], b1 = wb[col + 1];
            float x0 = acc[mt][nt][0] + b0, x1 = acc[mt][nt][1] + b1;
            float x2 = acc[mt][nt][2] + b0, x3 = acc[mt][nt][3] + b1;
            if (RELU) {
                x0 = fmaxf(x0, 0.f); x1 = fmaxf(x1, 0.f);
                x2 = fmaxf(x2, 0.f); x3 = fmaxf(x3, 0.f);
            }
            if (OUT16) {
                if (rowa < M)
                    *(__half2*)(g_x16 + (size_t)rowa * 128 + col) = __floats2half2_rn(x0, x1);
                if (rowb < M)
                    *(__half2*)(g_x16 + (size_t)rowb * 128 + col) = __floats2half2_rn(x2, x3);
            } else {
                if (rowa < M)
                    *(float2*)(outf + (size_t)rowa * 128 + col) = make_float2(x0, x1);
                if (rowb < M)
                    *(float2*)(outf + (size_t)rowb * 128 + col) = make_float2(x2, x3);
            }
        }
    }
}

// -------- launch --------
extern "C" void kernel_launch(void* const* d_in, const int* in_sizes, int n_in,
                              void* d_out, int out_size) {
    const int*   edge          = (const int*)d_in[0];
    const int*   src           = edge;
    const int*   dstp          = edge + EE;
    const int*   user_features = (const int*)d_in[1];
    const int*   item_features = (const int*)d_in[2];
    const int*   user_text     = (const int*)d_in[3];
    const int*   item_text     = (const int*)d_in[4];
    const float* user_id_emb   = (const float*)d_in[5];
    const float* item_id_emb   = (const float*)d_in[6];
    const float* user_feat_emb = (const float*)d_in[7];
    const float* item_feat_emb = (const float*)d_in[8];
    const float* word_emb      = (const float*)d_in[9];
    const float* user_projW    = (const float*)d_in[10];
    const float* user_projb    = (const float*)d_in[11];
    const float* item_projW    = (const float*)d_in[12];
    const float* item_projb    = (const float*)d_in[13];
    const float* w0W = (const float*)d_in[14];
    const float* w0b = (const float*)d_in[15];
    const float* w1W = (const float*)d_in[16];
    const float* w1b = (const float*)d_in[17];
    const float* v0W = (const float*)d_in[18];
    const float* v0b = (const float*)d_in[19];
    const float* v1W = (const float*)d_in[20];
    const float* v1b = (const float*)d_in[21];

    const int PROJ_SMEM = (3 * 128 * PSTR + 2 * 128 * PSTR) * 2;                 // 51200
    const int SAGE_SMEM = (3 * 128 * SSTR + 2 * 128 * SSTR) * 2 + 128 * 128 * 2; // 63488
    cudaFuncSetAttribute(proj_fill, cudaFuncAttributeMaxDynamicSharedMemorySize, PROJ_SMEM);
    cudaFuncSetAttribute(sage_layer<true, true>,   cudaFuncAttributeMaxDynamicSharedMemorySize, SAGE_SMEM);
    cudaFuncSetAttribute(sage_layer<false, false>, cudaFuncAttributeMaxDynamicSharedMemorySize, SAGE_SMEM);

    // 0: tables->bf16, weights->fp16^T, zero deg
    prep_kernel<<<2048, 256>>>(user_feat_emb, item_feat_emb, word_emb,
                               user_projW, item_projW, w0W, w1W, v0W, v1W);
    // 1: embed fp16 (+ deg counting riding along)
    embed_deg_kernel<<<EMB_BLKS + EDGE_BLKS, 256>>>(
        user_features, item_features, user_text, item_text, dstp);
    // 2-4: exclusive scan of degrees
    scan1_kernel<<<NBLK, 256>>>();
    scan2_kernel<<<1, 1024>>>();
    scan3_kernel<<<(NNODE + 255) / 256, 256>>>();
    // 5: fp16 projection GEMM (+ CSR fill riding along) -> g_x16
    proj_fill<<<PROJ_BLKS + EDGE_BLKS, 256, PROJ_SMEM>>>(
        user_projb, item_projb, user_id_emb, item_id_emb, src, dstp);

    // ----- layer 0 -----
    agg_kernel<<<(NNODE * 32 + 255) / 256, 256>>>();
    sage_layer<true, true><<<(NNODE + 127) / 128, 256, SAGE_SMEM>>>(
        OFF_V0, v0b, OFF_W0, w0b, nullptr, NNODE);

    // ----- layer 1 -----
    agg_kernel<<<(NNODE * 32 + 255) / 256, 256>>>();
    sage_layer<false, false><<<(NNODE + 127) / 128, 256, SAGE_SMEM>>>(
        OFF_V1, v1b, OFF_W1, w1b, (float*)d_out, NNODE);
}